// round 7
// baseline (speedup 1.0000x reference)
#include <cuda_runtime.h>
#include <cuda_bf16.h>
#include <cstdint>

// BrainSphereCNN on GB300. Middle 14 layers [N,896]@[896,128] on mma.sync
// bf16 3-term split (Ahi*Bhi + Ahi*Blo + Alo*Bhi, known rel_err ~1.1e-4).
// Round 7: K-chunk 32 (smem stage 40KB, double-buffered 80KB) -> 2 CTAs/SM
// so independent CTAs cover each other's syncs; reg budget kept <=64.

#define NN    40962
#define C     128
#define NB0   641
#define NBM   321
#define NCLS  36
#define EPSBN 1e-5f
#define NLAY  14

// ---------------- device scratch ----------------
__device__ float          g_Y[(size_t)NN * C];
__device__ __nv_bfloat16  g_Xhi[(size_t)NN * C];
__device__ __nv_bfloat16  g_Xlo[(size_t)NN * C];
__device__ __nv_bfloat16  g_Whi[(size_t)NLAY * C * 896];  // W^T hi [l][n][k]
__device__ __nv_bfloat16  g_Wlo[(size_t)NLAY * C * 896];
__device__ float          g_psum[NB0 * C];
__device__ float          g_psq [NB0 * C];
__device__ float          g_scale[C];
__device__ float          g_shift[C];

// ---------------- PTX helpers ----------------
__device__ __forceinline__ uint32_t smem_u32(const void* p) {
    uint32_t a;
    asm("{ .reg .u64 t; cvta.to.shared.u64 t, %1; cvt.u32.u64 %0, t; }" : "=r"(a) : "l"(p));
    return a;
}

#define LDSM_X4(r0, r1, r2, r3, addr) \
    asm volatile("ldmatrix.sync.aligned.m8n8.x4.shared.b16 {%0,%1,%2,%3}, [%4];" \
                 : "=r"(r0), "=r"(r1), "=r"(r2), "=r"(r3) : "r"(addr))

#define MMA16816(d0, d1, d2, d3, a0, a1, a2, a3, b0, b1) \
    asm volatile("mma.sync.aligned.m16n8k16.row.col.f32.bf16.bf16.f32 " \
                 "{%0,%1,%2,%3}, {%4,%5,%6,%7}, {%8,%9}, {%0,%1,%2,%3};" \
                 : "+f"(d0), "+f"(d1), "+f"(d2), "+f"(d3) \
                 : "r"(a0), "r"(a1), "r"(a2), "r"(a3), "r"(b0), "r"(b1))

#define CP16(dst, src) \
    asm volatile("cp.async.cg.shared.global [%0], [%1], 16;" :: "r"(dst), "l"(src) : "memory")
#define CP_COMMIT() asm volatile("cp.async.commit_group;" ::: "memory")
#define CP_WAIT(n)  asm volatile("cp.async.wait_group %0;" :: "n"(n) : "memory")

// ---------------- weight prep: W[l][k][n] -> W^T hi/lo [l][n][k] bf16 --------
__global__ void prep_w(const float* __restrict__ Wm) {
    __shared__ float tile[32][33];
    const int l = blockIdx.z, k0 = blockIdx.x * 32, n0 = blockIdx.y * 32;
    const int tx = threadIdx.x, ty = threadIdx.y;
    tile[ty][tx] = Wm[((size_t)l * 896 + k0 + ty) * 128 + n0 + tx];
    __syncthreads();
    float w = tile[tx][ty];
    __nv_bfloat16 hi = __float2bfloat16_rn(w);
    __nv_bfloat16 lo = __float2bfloat16_rn(w - __bfloat162float(hi));
    size_t o = ((size_t)l * 128 + n0 + ty) * 896 + (k0 + tx);
    g_Whi[o] = hi;
    g_Wlo[o] = lo;
}

// ---------------- layer 0: [N,21]@[21,128] fp32 ----------------
__global__ __launch_bounds__(128) void layer0_kernel(
    const float* __restrict__ x, const int* __restrict__ idx,
    const float* __restrict__ W0, const float* __restrict__ b0)
{
    __shared__ float sA[64 * 21];
    const int t = threadIdx.x;
    const int m0 = blockIdx.x * 64;
    for (int e = t; e < 64 * 21; e += 128) {
        int r = e / 21, k = e - r * 21;
        int m = m0 + r;
        float v = 0.f;
        if (m < NN) {
            int j = k / 3, c = k - j * 3;
            v = x[idx[m * 7 + j] * 3 + c];
        }
        sA[e] = v;
    }
    __syncthreads();
    float w[21];
#pragma unroll
    for (int k = 0; k < 21; k++) w[k] = W0[k * C + t];
    const float bias = b0[t];
    float s = 0.f, sq = 0.f;
    int rows = NN - m0; if (rows > 64) rows = 64;
    for (int r = 0; r < rows; r++) {
        float acc = bias;
#pragma unroll
        for (int k = 0; k < 21; k++) acc = fmaf(sA[r * 21 + k], w[k], acc);
        g_Y[(size_t)(m0 + r) * C + t] = acc;
        s += acc; sq += acc * acc;
    }
    g_psum[blockIdx.x * C + t] = s;
    g_psq [blockIdx.x * C + t] = sq;
}

// ---------------- BN stats finalize ----------------
__global__ __launch_bounds__(1024) void stats_final(int nblk, const float* __restrict__ g,
                                                    const float* __restrict__ be)
{
    __shared__ float sS[8][128], sQ[8][128];
    const int t = threadIdx.x;
    const int ch = t & 127, sl = t >> 7;
    float s = 0.f, q = 0.f;
    for (int b = sl; b < nblk; b += 8) {
        s += g_psum[b * C + ch];
        q += g_psq [b * C + ch];
    }
    sS[sl][ch] = s; sQ[sl][ch] = q;
    __syncthreads();
    if (t < 128) {
        float S = 0.f, Q = 0.f;
#pragma unroll
        for (int u = 0; u < 8; u++) { S += sS[u][t]; Q += sQ[u][t]; }
        const float inv_n = 1.f / (float)NN;
        float mu  = S * inv_n;
        float var = Q * inv_n - mu * mu;
        float sc  = g[t] * rsqrtf(var + EPSBN);
        g_scale[t] = sc;
        g_shift[t] = be[t] - mu * sc;
    }
}

// ---------------- convert: Y -> bf16 hi/lo (affine + ReLU) ----------------
__global__ __launch_bounds__(256) void convert_kernel() {
    int e = blockIdx.x * 256 + threadIdx.x;
    if (e >= NN * 32) return;
    const int c0 = (e & 31) * 4;
    float4 y = ((const float4*)g_Y)[e];
    float h0 = fmaxf(fmaf(y.x, g_scale[c0 + 0], g_shift[c0 + 0]), 0.f);
    float h1 = fmaxf(fmaf(y.y, g_scale[c0 + 1], g_shift[c0 + 1]), 0.f);
    float h2 = fmaxf(fmaf(y.z, g_scale[c0 + 2], g_shift[c0 + 2]), 0.f);
    float h3 = fmaxf(fmaf(y.w, g_scale[c0 + 3], g_shift[c0 + 3]), 0.f);
    __nv_bfloat16 a0 = __float2bfloat16_rn(h0), a1 = __float2bfloat16_rn(h1);
    __nv_bfloat16 a2 = __float2bfloat16_rn(h2), a3 = __float2bfloat16_rn(h3);
    __nv_bfloat16 l0 = __float2bfloat16_rn(h0 - __bfloat162float(a0));
    __nv_bfloat16 l1 = __float2bfloat16_rn(h1 - __bfloat162float(a1));
    __nv_bfloat16 l2 = __float2bfloat16_rn(h2 - __bfloat162float(a2));
    __nv_bfloat16 l3 = __float2bfloat16_rn(h3 - __bfloat162float(a3));
    uint2 ph, pl;
    ph.x = (uint32_t)__bfloat16_as_ushort(a0) | ((uint32_t)__bfloat16_as_ushort(a1) << 16);
    ph.y = (uint32_t)__bfloat16_as_ushort(a2) | ((uint32_t)__bfloat16_as_ushort(a3) << 16);
    pl.x = (uint32_t)__bfloat16_as_ushort(l0) | ((uint32_t)__bfloat16_as_ushort(l1) << 16);
    pl.y = (uint32_t)__bfloat16_as_ushort(l2) | ((uint32_t)__bfloat16_as_ushort(l3) << 16);
    ((uint2*)g_Xhi)[e] = ph;
    ((uint2*)g_Xlo)[e] = pl;
}

// ---------------- middle layer GEMM: bf16 3-term, K-chunk 32, 2 CTAs/SM ------
// 512 threads, 16 warps (4x4 grid of 32x32 warp tiles), 28 chunks of 32 halves.
// Stage: Ahi|Alo|Bhi|Blo, each 128 rows x 40-half pitch (80B) = 10240 B.
#define PITCH   40
#define BUFB    10240
#define STAGEB  (4 * BUFB)               // 40960
#define SM_IDX  (2 * STAGEB)             // 81920 : 896 ints
#define SM_REDS (SM_IDX + 3584)
#define SM_REDQ (SM_REDS + 2048)
#define GEMM_SMEM (SM_REDQ + 2048)       // 89600
#define STAGE_PITCH 132

__global__ void __launch_bounds__(512, 2)
gemm_mma(int layer, const int* __restrict__ idx, const float* __restrict__ bias)
{
    extern __shared__ char smp[];
    const uint32_t sb = smem_u32(smp);
    const int t    = threadIdx.x;
    const int lane = t & 31;
    const int wid  = t >> 5;
    const int wm   = wid >> 2;
    const int wn   = wid & 3;
    const int m0   = blockIdx.x * 128;

    const __nv_bfloat16* __restrict__ Whi = g_Whi + (size_t)layer * C * 896;
    const __nv_bfloat16* __restrict__ Wlo = g_Wlo + (size_t)layer * C * 896;

    int* sIdx = (int*)(smp + SM_IDX);
    for (int e = t; e < 896; e += 512) {
        int row = e / 7, j = e - row * 7;
        int m = m0 + row;
        sIdx[e] = (m < NN) ? idx[m * 7 + j] : 0;
    }
    __syncthreads();

    // loader: row = t>>2 (0..127), seg = t&3 (16B of the 64B chunk-row)
    const int grow = t >> 2;
    const int gseg = t & 3;
    const uint32_t dstOff = (uint32_t)grow * (PITCH * 2) + (uint32_t)gseg * 16;
    const __nv_bfloat16* bHrow = Whi + (size_t)grow * 896;
    const __nv_bfloat16* bLrow = Wlo + (size_t)grow * 896;

    // chunk c (0..27): neighbor j = c>>2, feature quarter h = c&3 (32 halves)
    auto issue = [&](int c, int s) {
        const int j = c >> 2, h = c & 3;
        const int nb = sIdx[grow * 7 + j];
        const char* aH = (const char*)(g_Xhi + (size_t)nb * C + h * 32) + gseg * 16;
        const char* aL = (const char*)(g_Xlo + (size_t)nb * C + h * 32) + gseg * 16;
        const char* bH = (const char*)(bHrow + c * 32) + gseg * 16;
        const char* bL = (const char*)(bLrow + c * 32) + gseg * 16;
        uint32_t base = sb + s * STAGEB + dstOff;
        CP16(base,            aH);
        CP16(base + BUFB,     aL);
        CP16(base + 2 * BUFB, bH);
        CP16(base + 3 * BUFB, bL);
        CP_COMMIT();
    };

    float d[2][4][4];
#pragma unroll
    for (int mt = 0; mt < 2; mt++)
#pragma unroll
        for (int nt = 0; nt < 4; nt++)
#pragma unroll
            for (int i = 0; i < 4; i++) d[mt][nt][i] = 0.f;

    const int a_row  = wm * 32 + (lane & 15);
    const int a_koff = (lane >> 4) * 8;
    const int b_n    = wn * 32 + (lane & 7) + ((lane >> 4) & 1) * 8;
    const int b_koff = ((lane >> 3) & 1) * 8;

    issue(0, 0);

    for (int c = 0; c < 28; c++) {
        const int s = c & 1;
        if (c + 1 < 28) {
            issue(c + 1, s ^ 1);
            CP_WAIT(1);
        } else {
            CP_WAIT(0);
        }
        __syncthreads();

        const uint32_t sAh = sb + s * STAGEB;
        const uint32_t sAl = sAh + BUFB;
        const uint32_t sBh = sAh + 2 * BUFB;
        const uint32_t sBl = sAh + 3 * BUFB;

        // two k16 steps per chunk; B-lo reuses B-hi registers to cap reg count
#pragma unroll
        for (int ks = 0; ks < 2; ks++) {
            uint32_t ahi[2][4], alo[2][4];
#pragma unroll
            for (int mt = 0; mt < 2; mt++) {
                uint32_t ra = sAh + ((a_row + mt * 16) * PITCH + ks * 16 + a_koff) * 2;
                LDSM_X4(ahi[mt][0], ahi[mt][1], ahi[mt][2], ahi[mt][3], ra);
                uint32_t rl = sAl + ((a_row + mt * 16) * PITCH + ks * 16 + a_koff) * 2;
                LDSM_X4(alo[mt][0], alo[mt][1], alo[mt][2], alo[mt][3], rl);
            }
            uint32_t bw[4][2];
#pragma unroll
            for (int p = 0; p < 2; p++) {
                uint32_t rb = sBh + ((b_n + p * 16) * PITCH + ks * 16 + b_koff) * 2;
                uint32_t r0, r1, r2, r3;
                LDSM_X4(r0, r1, r2, r3, rb);
                bw[2 * p][0] = r0; bw[2 * p][1] = r1;
                bw[2 * p + 1][0] = r2; bw[2 * p + 1][1] = r3;
            }
#pragma unroll
            for (int mt = 0; mt < 2; mt++)
#pragma unroll
                for (int nt = 0; nt < 4; nt++) {
                    MMA16816(d[mt][nt][0], d[mt][nt][1], d[mt][nt][2], d[mt][nt][3],
                             ahi[mt][0], ahi[mt][1], ahi[mt][2], ahi[mt][3],
                             bw[nt][0], bw[nt][1]);
                    MMA16816(d[mt][nt][0], d[mt][nt][1], d[mt][nt][2], d[mt][nt][3],
                             alo[mt][0], alo[mt][1], alo[mt][2], alo[mt][3],
                             bw[nt][0], bw[nt][1]);
                }
            // reload B registers with the lo split, one more A-hi pass
#pragma unroll
            for (int p = 0; p < 2; p++) {
                uint32_t rb = sBl + ((b_n + p * 16) * PITCH + ks * 16 + b_koff) * 2;
                uint32_t r0, r1, r2, r3;
                LDSM_X4(r0, r1, r2, r3, rb);
                bw[2 * p][0] = r0; bw[2 * p][1] = r1;
                bw[2 * p + 1][0] = r2; bw[2 * p + 1][1] = r3;
            }
#pragma unroll
            for (int mt = 0; mt < 2; mt++)
#pragma unroll
                for (int nt = 0; nt < 4; nt++)
                    MMA16816(d[mt][nt][0], d[mt][nt][1], d[mt][nt][2], d[mt][nt][3],
                             ahi[mt][0], ahi[mt][1], ahi[mt][2], ahi[mt][3],
                             bw[nt][0], bw[nt][1]);
        }
        __syncthreads();
    }

    // ---- epilogue: stage fp32, add bias, store Y, deterministic BN partials ----
    float* stage = (float*)smp;          // 128 x 132 x 4 = 67584 <= 81920
#pragma unroll
    for (int mt = 0; mt < 2; mt++)
#pragma unroll
        for (int nt = 0; nt < 4; nt++)
#pragma unroll
            for (int i = 0; i < 4; i++) {
                int row = wm * 32 + mt * 16 + (lane >> 2) + ((i >> 1) << 3);
                int col = wn * 32 + nt * 8 + ((lane & 3) << 1) + (i & 1);
                stage[row * STAGE_PITCH + col] = d[mt][nt][i] + __ldg(&bias[col]);
            }
    __syncthreads();

    {
        const int col = t & 127, part = t >> 7;
        float s = 0.f, q = 0.f;
        for (int r = 0; r < 32; r++) {
            int row = part * 32 + r;
            int m = m0 + row;
            float v = stage[row * STAGE_PITCH + col];
            if (m < NN) {
                g_Y[(size_t)m * C + col] = v;
                s += v; q += v * v;
            }
        }
        ((float*)(smp + SM_REDS))[part * 128 + col] = s;
        ((float*)(smp + SM_REDQ))[part * 128 + col] = q;
    }
    __syncthreads();
    if (t < 128) {
        float s = 0.f, q = 0.f;
#pragma unroll
        for (int u = 0; u < 4; u++) {
            s += ((float*)(smp + SM_REDS))[u * 128 + t];
            q += ((float*)(smp + SM_REDQ))[u * 128 + t];
        }
        g_psum[blockIdx.x * C + t] = s;
        g_psq [blockIdx.x * C + t] = q;
    }
}

// ---------------- final layer: [N,896]@[896,36] fp32 ----------------
__global__ __launch_bounds__(256, 2) void final_kernel(
    const int* __restrict__ idx,
    const float* __restrict__ Wl, const float* __restrict__ bl,
    float* __restrict__ out)
{
    const float* __restrict__ Hin = g_Y;
    __shared__ float sA[32 * 132];
    __shared__ float sB[32 * 40];
    __shared__ int   sIdx[128 * 7];
    __shared__ float sSc[128];
    __shared__ float sSh[128];

    const int t  = threadIdx.x;
    const int m0 = blockIdx.x * 128;
    for (int e = t; e < 128 * 7; e += 256) {
        int m = m0 + e / 7;
        sIdx[e] = (m < NN) ? idx[m * 7 + (e - (e / 7) * 7)] : 0;
    }
    if (t < 128) { sSc[t] = g_scale[t]; sSh[t] = g_shift[t]; }
    __syncthreads();

    const int ty = t >> 4, tx = t & 15;
    const int lrow = t >> 3, lk = (t & 7) << 2;
    const bool active = (tx < 12);
    const int cbase = active ? tx * 3 : 0;

    float acc[8][3];
#pragma unroll
    for (int i = 0; i < 8; i++)
#pragma unroll
        for (int jj = 0; jj < 3; jj++) acc[i][jj] = 0.f;

#pragma unroll 1
    for (int kt = 0; kt < 28; kt++) {
        const int j  = kt >> 2;
        const int cc = ((kt & 3) << 5) + lk;
        const float sc0 = sSc[cc], sc1 = sSc[cc + 1], sc2 = sSc[cc + 2], sc3 = sSc[cc + 3];
        const float sh0 = sSh[cc], sh1 = sSh[cc + 1], sh2 = sSh[cc + 2], sh3 = sSh[cc + 3];
#pragma unroll
        for (int p = 0; p < 4; p++) {
            int row = lrow + (p << 5);
            int nb  = sIdx[row * 7 + j];
            float4 v = *reinterpret_cast<const float4*>(&Hin[(size_t)nb * C + cc]);
            sA[(lk + 0) * 132 + row] = fmaxf(fmaf(v.x, sc0, sh0), 0.f);
            sA[(lk + 1) * 132 + row] = fmaxf(fmaf(v.y, sc1, sh1), 0.f);
            sA[(lk + 2) * 132 + row] = fmaxf(fmaf(v.z, sc2, sh2), 0.f);
            sA[(lk + 3) * 132 + row] = fmaxf(fmaf(v.w, sc3, sh3), 0.f);
        }
        for (int e = t; e < 32 * 36; e += 256) {
            int kr = e / 36, nc = e - kr * 36;
            sB[kr * 40 + nc] = Wl[(size_t)(kt * 32 + kr) * 36 + nc];
        }
        __syncthreads();
#pragma unroll 8
        for (int k = 0; k < 32; k++) {
            float4 aA = *reinterpret_cast<const float4*>(&sA[k * 132 + (ty << 3)]);
            float4 aB = *reinterpret_cast<const float4*>(&sA[k * 132 + (ty << 3) + 4]);
            float af[8] = { aA.x, aA.y, aA.z, aA.w, aB.x, aB.y, aB.z, aB.w };
            float b0v = sB[k * 40 + cbase];
            float b1v = sB[k * 40 + cbase + 1];
            float b2v = sB[k * 40 + cbase + 2];
#pragma unroll
            for (int i = 0; i < 8; i++) {
                acc[i][0] = fmaf(af[i], b0v, acc[i][0]);
                acc[i][1] = fmaf(af[i], b1v, acc[i][1]);
                acc[i][2] = fmaf(af[i], b2v, acc[i][2]);
            }
        }
        __syncthreads();
    }

    if (active) {
        float bb0 = bl[cbase], bb1 = bl[cbase + 1], bb2 = bl[cbase + 2];
#pragma unroll
        for (int i = 0; i < 8; i++) {
            int m = m0 + (ty << 3) + i;
            if (m < NN) {
                out[(size_t)m * NCLS + cbase + 0] = acc[i][0] + bb0;
                out[(size_t)m * NCLS + cbase + 1] = acc[i][1] + bb1;
                out[(size_t)m * NCLS + cbase + 2] = acc[i][2] + bb2;
            }
        }
    }
}

// ---------------- launch ----------------
extern "C" void kernel_launch(void* const* d_in, const int* in_sizes, int n_in,
                              void* d_out, int out_size)
{
    const float* x   = (const float*)d_in[0];
    const int*   idx = (const int*)  d_in[1];
    const float* W0  = (const float*)d_in[2];
    const float* b0  = (const float*)d_in[3];
    const float* g0  = (const float*)d_in[4];
    const float* be0 = (const float*)d_in[5];
    const float* Wm  = (const float*)d_in[6];
    const float* bm  = (const float*)d_in[7];
    const float* gm  = (const float*)d_in[8];
    const float* bem = (const float*)d_in[9];
    const float* Wl  = (const float*)d_in[10];
    const float* bl  = (const float*)d_in[11];
    float* out = (float*)d_out;

    static int smem_set = 0;
    if (!smem_set) {
        cudaFuncSetAttribute(gemm_mma, cudaFuncAttributeMaxDynamicSharedMemorySize, GEMM_SMEM);
        smem_set = 1;
    }

    prep_w<<<dim3(28, 4, NLAY), dim3(32, 32)>>>(Wm);
    layer0_kernel<<<NB0, 128>>>(x, idx, W0, b0);
    stats_final<<<1, 1024>>>(NB0, g0, be0);
    convert_kernel<<<(NN * 32 + 255) / 256, 256>>>();

    for (int l = 0; l < NLAY; l++) {
        gemm_mma<<<NBM, 512, GEMM_SMEM>>>(l, idx, bm + (size_t)l * C);
        stats_final<<<1, 1024>>>(NBM, gm + (size_t)l * C, bem + (size_t)l * C);
        if (l < NLAY - 1)
            convert_kernel<<<(NN * 32 + 255) / 256, 256>>>();
    }

    final_kernel<<<NBM, 256>>>(idx, Wl, bl, out);
}

// round 8
// speedup vs baseline: 1.0660x; 1.0660x over previous
#include <cuda_runtime.h>
#include <cuda_fp16.h>
#include <cstdint>

// BrainSphereCNN on GB300. Middle 14 layers [N,896]@[896,128] on mma.sync.
// Round 8: fp16 hi/lo split (residual 2^-22). Main term Ahi*Whi in f32-acc
// MMA; both cross terms (Ahi*Wlo + Alo*Whi, lo pre-scaled x2048 to stay in
// fp16 normal range) share ONE f16-acc MMA accumulator (2x rate if sm_103
// runs f16-acc at consumer rate). BM=64 tiles (641 CTAs, occ 2) to cut the
// wave-quantization tail from 3.0 to 2.5 wave-equivalents.

#define NN    40962
#define C     128
#define NB0   641
#define NBM   641
#define NCLS  36
#define EPSBN 1e-5f
#define NLAY  14
#define LOSCALE 2048.0f
#define INV_LOSCALE (1.0f / 2048.0f)

// ---------------- device scratch ----------------
__device__ float   g_Y[(size_t)NN * C];
__device__ __half  g_Xhi[(size_t)NN * C];          // post-BN/ReLU fp16 hi
__device__ __half  g_Xlo[(size_t)NN * C];          // fp16 lo residual * 2048
__device__ __half  g_Whi[(size_t)NLAY * C * 896];  // W^T hi [l][n][k]
__device__ __half  g_Wlo[(size_t)NLAY * C * 896];  // W^T lo * 2048
__device__ float   g_psum[NB0 * C];
__device__ float   g_psq [NB0 * C];
__device__ float   g_scale[C];
__device__ float   g_shift[C];

// ---------------- PTX helpers ----------------
__device__ __forceinline__ uint32_t smem_u32(const void* p) {
    uint32_t a;
    asm("{ .reg .u64 t; cvta.to.shared.u64 t, %1; cvt.u32.u64 %0, t; }" : "=r"(a) : "l"(p));
    return a;
}

#define LDSM_X4(r0, r1, r2, r3, addr) \
    asm volatile("ldmatrix.sync.aligned.m8n8.x4.shared.b16 {%0,%1,%2,%3}, [%4];" \
                 : "=r"(r0), "=r"(r1), "=r"(r2), "=r"(r3) : "r"(addr))

// fp16 operands, fp32 accumulator (main term)
#define MMA_F32(d0, d1, d2, d3, a0, a1, a2, a3, b0, b1) \
    asm volatile("mma.sync.aligned.m16n8k16.row.col.f32.f16.f16.f32 " \
                 "{%0,%1,%2,%3}, {%4,%5,%6,%7}, {%8,%9}, {%0,%1,%2,%3};" \
                 : "+f"(d0), "+f"(d1), "+f"(d2), "+f"(d3) \
                 : "r"(a0), "r"(a1), "r"(a2), "r"(a3), "r"(b0), "r"(b1))

// fp16 operands, fp16 accumulator (cross terms)
#define MMA_F16(c0, c1, a0, a1, a2, a3, b0, b1) \
    asm volatile("mma.sync.aligned.m16n8k16.row.col.f16.f16.f16.f16 " \
                 "{%0,%1}, {%2,%3,%4,%5}, {%6,%7}, {%0,%1};" \
                 : "+r"(c0), "+r"(c1) \
                 : "r"(a0), "r"(a1), "r"(a2), "r"(a3), "r"(b0), "r"(b1))

#define CP16(dst, src) \
    asm volatile("cp.async.cg.shared.global [%0], [%1], 16;" :: "r"(dst), "l"(src) : "memory")
#define CP_COMMIT() asm volatile("cp.async.commit_group;" ::: "memory")
#define CP_WAIT(n)  asm volatile("cp.async.wait_group %0;" :: "n"(n) : "memory")

// ---------------- weight prep: W[l][k][n] -> W^T hi/lo fp16 [l][n][k] --------
__global__ void prep_w(const float* __restrict__ Wm) {
    __shared__ float tile[32][33];
    const int l = blockIdx.z, k0 = blockIdx.x * 32, n0 = blockIdx.y * 32;
    const int tx = threadIdx.x, ty = threadIdx.y;
    tile[ty][tx] = Wm[((size_t)l * 896 + k0 + ty) * 128 + n0 + tx];
    __syncthreads();
    float w = tile[tx][ty];
    __half hi = __float2half_rn(w);
    __half lo = __float2half_rn((w - __half2float(hi)) * LOSCALE);
    size_t o = ((size_t)l * 128 + n0 + ty) * 896 + (k0 + tx);
    g_Whi[o] = hi;
    g_Wlo[o] = lo;
}

// ---------------- layer 0: [N,21]@[21,128] fp32 ----------------
__global__ __launch_bounds__(128) void layer0_kernel(
    const float* __restrict__ x, const int* __restrict__ idx,
    const float* __restrict__ W0, const float* __restrict__ b0)
{
    __shared__ float sA[64 * 21];
    const int t = threadIdx.x;
    const int m0 = blockIdx.x * 64;
    for (int e = t; e < 64 * 21; e += 128) {
        int r = e / 21, k = e - r * 21;
        int m = m0 + r;
        float v = 0.f;
        if (m < NN) {
            int j = k / 3, c = k - j * 3;
            v = x[idx[m * 7 + j] * 3 + c];
        }
        sA[e] = v;
    }
    __syncthreads();
    float w[21];
#pragma unroll
    for (int k = 0; k < 21; k++) w[k] = W0[k * C + t];
    const float bias = b0[t];
    float s = 0.f, sq = 0.f;
    int rows = NN - m0; if (rows > 64) rows = 64;
    for (int r = 0; r < rows; r++) {
        float acc = bias;
#pragma unroll
        for (int k = 0; k < 21; k++) acc = fmaf(sA[r * 21 + k], w[k], acc);
        g_Y[(size_t)(m0 + r) * C + t] = acc;
        s += acc; sq += acc * acc;
    }
    g_psum[blockIdx.x * C + t] = s;
    g_psq [blockIdx.x * C + t] = sq;
}

// ---------------- BN stats finalize ----------------
__global__ __launch_bounds__(1024) void stats_final(int nblk, const float* __restrict__ g,
                                                    const float* __restrict__ be)
{
    __shared__ float sS[8][128], sQ[8][128];
    const int t = threadIdx.x;
    const int ch = t & 127, sl = t >> 7;
    float s = 0.f, q = 0.f;
    for (int b = sl; b < nblk; b += 8) {
        s += g_psum[b * C + ch];
        q += g_psq [b * C + ch];
    }
    sS[sl][ch] = s; sQ[sl][ch] = q;
    __syncthreads();
    if (t < 128) {
        float S = 0.f, Q = 0.f;
#pragma unroll
        for (int u = 0; u < 8; u++) { S += sS[u][t]; Q += sQ[u][t]; }
        const float inv_n = 1.f / (float)NN;
        float mu  = S * inv_n;
        float var = Q * inv_n - mu * mu;
        float sc  = g[t] * rsqrtf(var + EPSBN);
        g_scale[t] = sc;
        g_shift[t] = be[t] - mu * sc;
    }
}

// ---------------- convert: Y -> fp16 hi + scaled lo (affine + ReLU) ----------
__global__ __launch_bounds__(256) void convert_kernel() {
    int e = blockIdx.x * 256 + threadIdx.x;
    if (e >= NN * 32) return;
    const int c0 = (e & 31) * 4;
    float4 y = ((const float4*)g_Y)[e];
    float h0 = fmaxf(fmaf(y.x, g_scale[c0 + 0], g_shift[c0 + 0]), 0.f);
    float h1 = fmaxf(fmaf(y.y, g_scale[c0 + 1], g_shift[c0 + 1]), 0.f);
    float h2 = fmaxf(fmaf(y.z, g_scale[c0 + 2], g_shift[c0 + 2]), 0.f);
    float h3 = fmaxf(fmaf(y.w, g_scale[c0 + 3], g_shift[c0 + 3]), 0.f);
    __half a0 = __float2half_rn(h0), a1 = __float2half_rn(h1);
    __half a2 = __float2half_rn(h2), a3 = __float2half_rn(h3);
    __half l0 = __float2half_rn((h0 - __half2float(a0)) * LOSCALE);
    __half l1 = __float2half_rn((h1 - __half2float(a1)) * LOSCALE);
    __half l2 = __float2half_rn((h2 - __half2float(a2)) * LOSCALE);
    __half l3 = __float2half_rn((h3 - __half2float(a3)) * LOSCALE);
    uint2 ph, pl;
    ph.x = (uint32_t)__half_as_ushort(a0) | ((uint32_t)__half_as_ushort(a1) << 16);
    ph.y = (uint32_t)__half_as_ushort(a2) | ((uint32_t)__half_as_ushort(a3) << 16);
    pl.x = (uint32_t)__half_as_ushort(l0) | ((uint32_t)__half_as_ushort(l1) << 16);
    pl.y = (uint32_t)__half_as_ushort(l2) | ((uint32_t)__half_as_ushort(l3) << 16);
    ((uint2*)g_Xhi)[e] = ph;
    ((uint2*)g_Xlo)[e] = pl;
}

// ---------------- middle layer GEMM: fp16 split, BM=64, occ 2 ----------------
// 256 threads, 8 warps (2x4 grid of 32x32 warp tiles), 14 chunks of 64 halves.
// Stage: Ahi(64x72h)|Alo|Bhi(128x72h)|Blo = 55296 B; double-buffered 110592 B.
#define PITCH   72
#define ABUF    9216                     // 64 * 72 * 2
#define WBUF    18432                    // 128 * 72 * 2
#define STAGEB  (2 * ABUF + 2 * WBUF)    // 55296
#define GEMM_SMEM (2 * STAGEB)           // 110592
#define STAGE_PITCH 132
#define SM_REDS STAGEB                   // epilogue overlay (stage-1 region)
#define SM_REDQ (STAGEB + 1024)

__global__ void __launch_bounds__(256, 2)
gemm_mma(int layer, const int* __restrict__ idx, const float* __restrict__ bias)
{
    extern __shared__ char smp[];
    const uint32_t sb = smem_u32(smp);
    const int t    = threadIdx.x;
    const int lane = t & 31;
    const int wid  = t >> 5;
    const int wm   = wid >> 2;           // 0..1
    const int wn   = wid & 3;            // 0..3
    const int m0   = blockIdx.x * 64;

    const __half* __restrict__ Whi = g_Whi + (size_t)layer * C * 896;
    const __half* __restrict__ Wlo = g_Wlo + (size_t)layer * C * 896;

    // per-thread neighbor indices for the A-loader row
    const int grow = t >> 2;             // 0..63
    const int gq   = t & 3;              // 32B segment
    int nbr[7];
    {
        int m = m0 + grow;
        int mm = (m < NN) ? m : 0;
#pragma unroll
        for (int j = 0; j < 7; j++) nbr[j] = idx[mm * 7 + j];
    }
    // W loader: 2 threads per W row (64B each)
    const int wrow = t >> 1;             // 0..127
    const int wq   = t & 1;
    const __half* wHsrc = Whi + (size_t)wrow * 896;
    const __half* wLsrc = Wlo + (size_t)wrow * 896;

    const uint32_t aDst = (uint32_t)grow * (PITCH * 2) + (uint32_t)gq * 32;
    const uint32_t wDst = (uint32_t)wrow * (PITCH * 2) + (uint32_t)wq * 64;

    auto issue = [&](int c, int s) {
        const int j = c >> 1, h = c & 1;
        const int nb = nbr[j];
        const char* aH = (const char*)(g_Xhi + (size_t)nb * C + h * 64) + gq * 32;
        const char* aL = (const char*)(g_Xlo + (size_t)nb * C + h * 64) + gq * 32;
        const char* wH = (const char*)(wHsrc + c * 64) + wq * 64;
        const char* wL = (const char*)(wLsrc + c * 64) + wq * 64;
        uint32_t base = sb + s * STAGEB;
        CP16(base + aDst,             aH);
        CP16(base + aDst + 16,        aH + 16);
        CP16(base + ABUF + aDst,      aL);
        CP16(base + ABUF + aDst + 16, aL + 16);
        uint32_t bh = base + 2 * ABUF + wDst;
        CP16(bh,      wH);
        CP16(bh + 16, wH + 16);
        CP16(bh + 32, wH + 32);
        CP16(bh + 48, wH + 48);
        uint32_t blb = base + 2 * ABUF + WBUF + wDst;
        CP16(blb,      wL);
        CP16(blb + 16, wL + 16);
        CP16(blb + 32, wL + 32);
        CP16(blb + 48, wL + 48);
        CP_COMMIT();
    };

    float    d[2][4][4];                 // fp32 main accumulators
    uint32_t c16[2][4][2];               // fp16 cross accumulators (scaled x2048)
#pragma unroll
    for (int mt = 0; mt < 2; mt++)
#pragma unroll
        for (int nt = 0; nt < 4; nt++) {
#pragma unroll
            for (int i = 0; i < 4; i++) d[mt][nt][i] = 0.f;
            c16[mt][nt][0] = 0u; c16[mt][nt][1] = 0u;
        }

    const int a_row  = wm * 32 + (lane & 15);
    const int a_koff = (lane >> 4) * 8;
    const int b_n    = wn * 32 + (lane & 7) + ((lane >> 4) & 1) * 8;
    const int b_koff = ((lane >> 3) & 1) * 8;

    issue(0, 0);

    for (int c = 0; c < 14; c++) {
        const int s = c & 1;
        if (c + 1 < 14) {
            issue(c + 1, s ^ 1);
            CP_WAIT(1);
        } else {
            CP_WAIT(0);
        }
        __syncthreads();

        const uint32_t sAh = sb + s * STAGEB;
        const uint32_t sAl = sAh + ABUF;
        const uint32_t sBh = sAh + 2 * ABUF;
        const uint32_t sBl = sBh + WBUF;

#pragma unroll
        for (int ks = 0; ks < 4; ks++) {
            uint32_t ahi[2][4], alo[2][4];
#pragma unroll
            for (int mt = 0; mt < 2; mt++) {
                uint32_t ra = sAh + ((a_row + mt * 16) * PITCH + ks * 16 + a_koff) * 2;
                LDSM_X4(ahi[mt][0], ahi[mt][1], ahi[mt][2], ahi[mt][3], ra);
                uint32_t rl = sAl + ((a_row + mt * 16) * PITCH + ks * 16 + a_koff) * 2;
                LDSM_X4(alo[mt][0], alo[mt][1], alo[mt][2], alo[mt][3], rl);
            }
            uint32_t bh[4][2], bl[4][2];
#pragma unroll
            for (int p = 0; p < 2; p++) {
                uint32_t rb = sBh + ((b_n + p * 16) * PITCH + ks * 16 + b_koff) * 2;
                uint32_t r0, r1, r2, r3;
                LDSM_X4(r0, r1, r2, r3, rb);
                bh[2 * p][0] = r0; bh[2 * p][1] = r1;
                bh[2 * p + 1][0] = r2; bh[2 * p + 1][1] = r3;
                uint32_t rbl = sBl + ((b_n + p * 16) * PITCH + ks * 16 + b_koff) * 2;
                LDSM_X4(r0, r1, r2, r3, rbl);
                bl[2 * p][0] = r0; bl[2 * p][1] = r1;
                bl[2 * p + 1][0] = r2; bl[2 * p + 1][1] = r3;
            }
#pragma unroll
            for (int mt = 0; mt < 2; mt++)
#pragma unroll
                for (int nt = 0; nt < 4; nt++) {
                    // main: f32 acc
                    MMA_F32(d[mt][nt][0], d[mt][nt][1], d[mt][nt][2], d[mt][nt][3],
                            ahi[mt][0], ahi[mt][1], ahi[mt][2], ahi[mt][3],
                            bh[nt][0], bh[nt][1]);
                    // cross: f16 acc (both terms pre-scaled x2048 on the lo side)
                    MMA_F16(c16[mt][nt][0], c16[mt][nt][1],
                            ahi[mt][0], ahi[mt][1], ahi[mt][2], ahi[mt][3],
                            bl[nt][0], bl[nt][1]);
                    MMA_F16(c16[mt][nt][0], c16[mt][nt][1],
                            alo[mt][0], alo[mt][1], alo[mt][2], alo[mt][3],
                            bh[nt][0], bh[nt][1]);
                }
        }
        __syncthreads();
    }

    // ---- epilogue: merge cross terms, add bias, store Y, BN partials ----
    float* stage = (float*)smp;          // 64 x 132 x 4 = 33792 (stage-0 region)
#pragma unroll
    for (int mt = 0; mt < 2; mt++)
#pragma unroll
        for (int nt = 0; nt < 4; nt++)
#pragma unroll
            for (int i = 0; i < 4; i++) {
                int row = wm * 32 + mt * 16 + (lane >> 2) + ((i >> 1) << 3);
                int col = wn * 32 + nt * 8 + ((lane & 3) << 1) + (i & 1);
                __half2 hc = *(__half2*)&c16[mt][nt][i >> 1];
                float cross = __half2float((i & 1) ? __high2half(hc) : __low2half(hc));
                stage[row * STAGE_PITCH + col] =
                    d[mt][nt][i] + cross * INV_LOSCALE + __ldg(&bias[col]);
            }
    __syncthreads();

    {
        const int col = t & 127, part = t >> 7;   // 2 parts x 32 rows
        float s = 0.f, q = 0.f;
        for (int r = 0; r < 32; r++) {
            int row = part * 32 + r;
            int m = m0 + row;
            float v = stage[row * STAGE_PITCH + col];
            if (m < NN) {
                g_Y[(size_t)m * C + col] = v;
                s += v; q += v * v;
            }
        }
        ((float*)(smp + SM_REDS))[part * 128 + col] = s;
        ((float*)(smp + SM_REDQ))[part * 128 + col] = q;
    }
    __syncthreads();
    if (t < 128) {
        float s = ((float*)(smp + SM_REDS))[t] + ((float*)(smp + SM_REDS))[128 + t];
        float q = ((float*)(smp + SM_REDQ))[t] + ((float*)(smp + SM_REDQ))[128 + t];
        g_psum[blockIdx.x * C + t] = s;
        g_psq [blockIdx.x * C + t] = q;
    }
}

// ---------------- final layer: [N,896]@[896,36] fp32 ----------------
__global__ __launch_bounds__(256, 2) void final_kernel(
    const int* __restrict__ idx,
    const float* __restrict__ Wl, const float* __restrict__ bl,
    float* __restrict__ out)
{
    const float* __restrict__ Hin = g_Y;
    __shared__ float sA[32 * 132];
    __shared__ float sB[32 * 40];
    __shared__ int   sIdx[128 * 7];
    __shared__ float sSc[128];
    __shared__ float sSh[128];

    const int t  = threadIdx.x;
    const int m0 = blockIdx.x * 128;
    for (int e = t; e < 128 * 7; e += 256) {
        int m = m0 + e / 7;
        sIdx[e] = (m < NN) ? idx[m * 7 + (e - (e / 7) * 7)] : 0;
    }
    if (t < 128) { sSc[t] = g_scale[t]; sSh[t] = g_shift[t]; }
    __syncthreads();

    const int ty = t >> 4, tx = t & 15;
    const int lrow = t >> 3, lk = (t & 7) << 2;
    const bool active = (tx < 12);
    const int cbase = active ? tx * 3 : 0;

    float acc[8][3];
#pragma unroll
    for (int i = 0; i < 8; i++)
#pragma unroll
        for (int jj = 0; jj < 3; jj++) acc[i][jj] = 0.f;

#pragma unroll 1
    for (int kt = 0; kt < 28; kt++) {
        const int j  = kt >> 2;
        const int cc = ((kt & 3) << 5) + lk;
        const float sc0 = sSc[cc], sc1 = sSc[cc + 1], sc2 = sSc[cc + 2], sc3 = sSc[cc + 3];
        const float sh0 = sSh[cc], sh1 = sSh[cc + 1], sh2 = sSh[cc + 2], sh3 = sSh[cc + 3];
#pragma unroll
        for (int p = 0; p < 4; p++) {
            int row = lrow + (p << 5);
            int nb  = sIdx[row * 7 + j];
            float4 v = *reinterpret_cast<const float4*>(&Hin[(size_t)nb * C + cc]);
            sA[(lk + 0) * 132 + row] = fmaxf(fmaf(v.x, sc0, sh0), 0.f);
            sA[(lk + 1) * 132 + row] = fmaxf(fmaf(v.y, sc1, sh1), 0.f);
            sA[(lk + 2) * 132 + row] = fmaxf(fmaf(v.z, sc2, sh2), 0.f);
            sA[(lk + 3) * 132 + row] = fmaxf(fmaf(v.w, sc3, sh3), 0.f);
        }
        for (int e = t; e < 32 * 36; e += 256) {
            int kr = e / 36, nc = e - kr * 36;
            sB[kr * 40 + nc] = Wl[(size_t)(kt * 32 + kr) * 36 + nc];
        }
        __syncthreads();
#pragma unroll 8
        for (int k = 0; k < 32; k++) {
            float4 aA = *reinterpret_cast<const float4*>(&sA[k * 132 + (ty << 3)]);
            float4 aB = *reinterpret_cast<const float4*>(&sA[k * 132 + (ty << 3) + 4]);
            float af[8] = { aA.x, aA.y, aA.z, aA.w, aB.x, aB.y, aB.z, aB.w };
            float b0v = sB[k * 40 + cbase];
            float b1v = sB[k * 40 + cbase + 1];
            float b2v = sB[k * 40 + cbase + 2];
#pragma unroll
            for (int i = 0; i < 8; i++) {
                acc[i][0] = fmaf(af[i], b0v, acc[i][0]);
                acc[i][1] = fmaf(af[i], b1v, acc[i][1]);
                acc[i][2] = fmaf(af[i], b2v, acc[i][2]);
            }
        }
        __syncthreads();
    }

    if (active) {
        float bb0 = bl[cbase], bb1 = bl[cbase + 1], bb2 = bl[cbase + 2];
#pragma unroll
        for (int i = 0; i < 8; i++) {
            int m = m0 + (ty << 3) + i;
            if (m < NN) {
                out[(size_t)m * NCLS + cbase + 0] = acc[i][0] + bb0;
                out[(size_t)m * NCLS + cbase + 1] = acc[i][1] + bb1;
                out[(size_t)m * NCLS + cbase + 2] = acc[i][2] + bb2;
            }
        }
    }
}

// ---------------- launch ----------------
extern "C" void kernel_launch(void* const* d_in, const int* in_sizes, int n_in,
                              void* d_out, int out_size)
{
    const float* x   = (const float*)d_in[0];
    const int*   idx = (const int*)  d_in[1];
    const float* W0  = (const float*)d_in[2];
    const float* b0  = (const float*)d_in[3];
    const float* g0  = (const float*)d_in[4];
    const float* be0 = (const float*)d_in[5];
    const float* Wm  = (const float*)d_in[6];
    const float* bm  = (const float*)d_in[7];
    const float* gm  = (const float*)d_in[8];
    const float* bem = (const float*)d_in[9];
    const float* Wl  = (const float*)d_in[10];
    const float* bl  = (const float*)d_in[11];
    float* out = (float*)d_out;

    cudaFuncSetAttribute(gemm_mma, cudaFuncAttributeMaxDynamicSharedMemorySize, GEMM_SMEM);

    prep_w<<<dim3(28, 4, NLAY), dim3(32, 32)>>>(Wm);
    layer0_kernel<<<NB0, 128>>>(x, idx, W0, b0);
    stats_final<<<1, 1024>>>(NB0, g0, be0);
    convert_kernel<<<(NN * 32 + 255) / 256, 256>>>();

    for (int l = 0; l < NLAY; l++) {
        gemm_mma<<<NBM, 256, GEMM_SMEM>>>(l, idx, bm + (size_t)l * C);
        stats_final<<<1, 1024>>>(NBM, gm + (size_t)l * C, bem + (size_t)l * C);
        if (l < NLAY - 1)
            convert_kernel<<<(NN * 32 + 255) / 256, 256>>>();
    }

    final_kernel<<<(NN + 127) / 128, 256>>>(idx, Wl, bl, out);
}

// round 9
// speedup vs baseline: 1.0707x; 1.0044x over previous
#include <cuda_runtime.h>
#include <cuda_fp16.h>
#include <cstdint>

// BrainSphereCNN on GB300. Round 9: single kernel per middle layer.
// - gather reads fp32 Y directly, applies BN affine+ReLU+fp16 hi/lo split
//   in registers (convert kernels eliminated; Y ping-pong buffered)
// - BN stats folded into the GEMM via last-block ticket (stats kernels gone)
// - mma.sync fp16: main term f32-acc, both cross terms share one f16-acc
//   (lo parts pre-scaled x2048), known rel_err ~1.8e-5

#define NN    40962
#define C     128
#define NB0   641
#define NBM   321
#define NCLS  36
#define EPSBN 1e-5f
#define NLAY  14
#define LOSCALE 2048.0f
#define INV_LOSCALE (1.0f / 2048.0f)

// ---------------- device scratch ----------------
__device__ float   g_Y[2ull * NN * C];             // ping-pong pre-BN outputs
__device__ __half  g_Whi[(size_t)NLAY * C * 896];  // W^T hi [l][n][k]
__device__ __half  g_Wlo[(size_t)NLAY * C * 896];  // W^T lo * 2048
__device__ float   g_psum[NB0 * C];
__device__ float   g_psq [NB0 * C];
__device__ float   g_scale[C];
__device__ float   g_shift[C];
__device__ int     g_ticket[NLAY];                 // zero-init; reset after use

// ---------------- PTX helpers ----------------
__device__ __forceinline__ uint32_t smem_u32(const void* p) {
    uint32_t a;
    asm("{ .reg .u64 t; cvta.to.shared.u64 t, %1; cvt.u32.u64 %0, t; }" : "=r"(a) : "l"(p));
    return a;
}

#define LDSM_X4(r0, r1, r2, r3, addr) \
    asm volatile("ldmatrix.sync.aligned.m8n8.x4.shared.b16 {%0,%1,%2,%3}, [%4];" \
                 : "=r"(r0), "=r"(r1), "=r"(r2), "=r"(r3) : "r"(addr))

#define MMA_F32(d0, d1, d2, d3, a0, a1, a2, a3, b0, b1) \
    asm volatile("mma.sync.aligned.m16n8k16.row.col.f32.f16.f16.f32 " \
                 "{%0,%1,%2,%3}, {%4,%5,%6,%7}, {%8,%9}, {%0,%1,%2,%3};" \
                 : "+f"(d0), "+f"(d1), "+f"(d2), "+f"(d3) \
                 : "r"(a0), "r"(a1), "r"(a2), "r"(a3), "r"(b0), "r"(b1))

#define MMA_F16(c0, c1, a0, a1, a2, a3, b0, b1) \
    asm volatile("mma.sync.aligned.m16n8k16.row.col.f16.f16.f16.f16 " \
                 "{%0,%1}, {%2,%3,%4,%5}, {%6,%7}, {%0,%1};" \
                 : "+r"(c0), "+r"(c1) \
                 : "r"(a0), "r"(a1), "r"(a2), "r"(a3), "r"(b0), "r"(b1))

#define CP16(dst, src) \
    asm volatile("cp.async.cg.shared.global [%0], [%1], 16;" :: "r"(dst), "l"(src) : "memory")
#define CP_COMMIT() asm volatile("cp.async.commit_group;" ::: "memory")
#define CP_WAIT(n)  asm volatile("cp.async.wait_group %0;" :: "n"(n) : "memory")

#define STS128(addr, x, y, z, w) \
    asm volatile("st.shared.v4.b32 [%0], {%1,%2,%3,%4};" :: "r"(addr), \
                 "r"(x), "r"(y), "r"(z), "r"(w) : "memory")

__device__ __forceinline__ uint32_t packh(float a, float b) {
    __half2 h = __floats2half2_rn(a, b);
    return *(uint32_t*)&h;
}

// ---------------- weight prep: W[l][k][n] -> W^T hi/lo fp16 [l][n][k] --------
__global__ void prep_w(const float* __restrict__ Wm) {
    __shared__ float tile[32][33];
    const int l = blockIdx.z, k0 = blockIdx.x * 32, n0 = blockIdx.y * 32;
    const int tx = threadIdx.x, ty = threadIdx.y;
    tile[ty][tx] = Wm[((size_t)l * 896 + k0 + ty) * 128 + n0 + tx];
    __syncthreads();
    float w = tile[tx][ty];
    __half hi = __float2half_rn(w);
    __half lo = __float2half_rn((w - __half2float(hi)) * LOSCALE);
    size_t o = ((size_t)l * 128 + n0 + ty) * 896 + (k0 + tx);
    g_Whi[o] = hi;
    g_Wlo[o] = lo;
}

// ---------------- layer 0: [N,21]@[21,128] fp32 ----------------
__global__ __launch_bounds__(128) void layer0_kernel(
    const float* __restrict__ x, const int* __restrict__ idx,
    const float* __restrict__ W0, const float* __restrict__ b0)
{
    __shared__ float sA[64 * 21];
    const int t = threadIdx.x;
    const int m0 = blockIdx.x * 64;
    for (int e = t; e < 64 * 21; e += 128) {
        int r = e / 21, k = e - r * 21;
        int m = m0 + r;
        float v = 0.f;
        if (m < NN) {
            int j = k / 3, c = k - j * 3;
            v = x[idx[m * 7 + j] * 3 + c];
        }
        sA[e] = v;
    }
    __syncthreads();
    float w[21];
#pragma unroll
    for (int k = 0; k < 21; k++) w[k] = W0[k * C + t];
    const float bias = b0[t];
    float s = 0.f, sq = 0.f;
    int rows = NN - m0; if (rows > 64) rows = 64;
    for (int r = 0; r < rows; r++) {
        float acc = bias;
#pragma unroll
        for (int k = 0; k < 21; k++) acc = fmaf(sA[r * 21 + k], w[k], acc);
        g_Y[(size_t)(m0 + r) * C + t] = acc;
        s += acc; sq += acc * acc;
    }
    g_psum[blockIdx.x * C + t] = s;
    g_psq [blockIdx.x * C + t] = sq;
}

// ---------------- BN stats finalize (layer 0 only) ----------------
__global__ __launch_bounds__(1024) void stats_final(int nblk, const float* __restrict__ g,
                                                    const float* __restrict__ be)
{
    __shared__ float sS[8][128], sQ[8][128];
    const int t = threadIdx.x;
    const int ch = t & 127, sl = t >> 7;
    float s = 0.f, q = 0.f;
    for (int b = sl; b < nblk; b += 8) {
        s += g_psum[b * C + ch];
        q += g_psq [b * C + ch];
    }
    sS[sl][ch] = s; sQ[sl][ch] = q;
    __syncthreads();
    if (t < 128) {
        float S = 0.f, Q = 0.f;
#pragma unroll
        for (int u = 0; u < 8; u++) { S += sS[u][t]; Q += sQ[u][t]; }
        const float inv_n = 1.f / (float)NN;
        float mu  = S * inv_n;
        float var = Q * inv_n - mu * mu;
        float sc  = g[t] * rsqrtf(var + EPSBN);
        g_scale[t] = sc;
        g_shift[t] = be[t] - mu * sc;
    }
}

// ---------------- middle layer GEMM: fused gather-convert + stats ------------
// 512 threads, 16 warps (4x4 grid of 32x32 warp tiles), 14 chunks of 64 halves.
// Stage: Ahi|Alo|Whi|Wlo, each 128 rows x 72-half pitch = 18432 B -> 73728/stage.
#define PITCH   72
#define BUFB    18432
#define STAGEB  (4 * BUFB)               // 73728
#define SM_REDS STAGEB                   // epilogue overlay (stage-1 region)
#define SM_REDQ (STAGEB + 2048)
#define SM_SC   (2 * STAGEB)             // 147456
#define SM_SH   (SM_SC + 512)
#define GEMM_SMEM (SM_SH + 512)          // 148480
#define STAGE_PITCH 132

__global__ void __launch_bounds__(512, 1)
gemm_mma(int layer, int cur, const int* __restrict__ idx,
         const float* __restrict__ bias,
         const float* __restrict__ gamma, const float* __restrict__ beta)
{
    extern __shared__ char smp[];
    const uint32_t sb = smem_u32(smp);
    const int t    = threadIdx.x;
    const int lane = t & 31;
    const int wid  = t >> 5;
    const int wm   = wid >> 2;
    const int wn   = wid & 3;
    const int m0   = blockIdx.x * 128;

    const float* __restrict__ Yin  = g_Y + (size_t)cur * NN * C;
    float*       __restrict__ Yout = g_Y + (size_t)(cur ^ 1) * NN * C;
    const __half* __restrict__ Whi = g_Whi + (size_t)layer * C * 896;
    const __half* __restrict__ Wlo = g_Wlo + (size_t)layer * C * 896;

    // loader mapping: grow = t>>2 (0..127 rows), gq = t&3 (16-float segment)
    const int grow = t >> 2;
    const int gq   = t & 3;
    int nbr[7];
    {
        int m = m0 + grow;
        int mm = (m < NN) ? m : 0;
#pragma unroll
        for (int j = 0; j < 7; j++) nbr[j] = idx[mm * 7 + j];
    }
    const __half* wHsrc = Whi + (size_t)grow * 896;   // W row = grow, 4 thr/row
    const __half* wLsrc = Wlo + (size_t)grow * 896;

    float* sSc = (float*)(smp + SM_SC);
    float* sSh = (float*)(smp + SM_SH);
    if (t < 128) { sSc[t] = g_scale[t]; sSh[t] = g_shift[t]; }
    __syncthreads();

    const uint32_t aDst = (uint32_t)grow * (PITCH * 2) + (uint32_t)gq * 32;  // bytes
    const uint32_t wDst = aDst;                                              // same map

    // W cp.async for chunk c into stage s
    auto issueW = [&](int c, int s) {
        const char* wH = (const char*)(wHsrc + c * 64) + gq * 32;
        const char* wL = (const char*)(wLsrc + c * 64) + gq * 32;
        uint32_t base = sb + s * STAGEB;
        CP16(base + 2 * BUFB + wDst,      wH);
        CP16(base + 2 * BUFB + wDst + 16, wH + 16);
        CP16(base + 3 * BUFB + wDst,      wL);
        CP16(base + 3 * BUFB + wDst + 16, wL + 16);
        CP_COMMIT();
    };

    // A prefetch: 16 fp32 values for chunk c
    float4 v0, v1, v2, v3;
    auto loadA = [&](int c) {
        const int j = c >> 1, h = c & 1;
        const float* src = Yin + (size_t)nbr[j] * C + h * 64 + gq * 16;
        v0 = __ldg((const float4*)(src + 0));
        v1 = __ldg((const float4*)(src + 4));
        v2 = __ldg((const float4*)(src + 8));
        v3 = __ldg((const float4*)(src + 12));
    };

    // convert staged A regs (affine+relu+split) and STS into stage s
    auto storeA = [&](int c, int s) {
        const int cb = (c & 1) * 64 + gq * 16;
        float p[16] = { v0.x, v0.y, v0.z, v0.w, v1.x, v1.y, v1.z, v1.w,
                        v2.x, v2.y, v2.z, v2.w, v3.x, v3.y, v3.z, v3.w };
        uint32_t hi[8], lo[8];
#pragma unroll
        for (int i = 0; i < 8; i++) {
            float h0 = fmaxf(fmaf(p[2*i],   sSc[cb + 2*i],   sSh[cb + 2*i]),   0.f);
            float h1 = fmaxf(fmaf(p[2*i+1], sSc[cb + 2*i+1], sSh[cb + 2*i+1]), 0.f);
            hi[i] = packh(h0, h1);
            __half2 hh = *(__half2*)&hi[i];
            lo[i] = packh((h0 - __half2float(__low2half(hh)))  * LOSCALE,
                          (h1 - __half2float(__high2half(hh))) * LOSCALE);
        }
        uint32_t base = sb + s * STAGEB + aDst;
        STS128(base,            hi[0], hi[1], hi[2], hi[3]);
        STS128(base + 16,       hi[4], hi[5], hi[6], hi[7]);
        STS128(base + BUFB,      lo[0], lo[1], lo[2], lo[3]);
        STS128(base + BUFB + 16, lo[4], lo[5], lo[6], lo[7]);
    };

    float    d[2][4][4];
    uint32_t c16[2][4][2];
#pragma unroll
    for (int mt = 0; mt < 2; mt++)
#pragma unroll
        for (int nt = 0; nt < 4; nt++) {
#pragma unroll
            for (int i = 0; i < 4; i++) d[mt][nt][i] = 0.f;
            c16[mt][nt][0] = 0u; c16[mt][nt][1] = 0u;
        }

    const int a_row  = wm * 32 + (lane & 15);
    const int a_koff = (lane >> 4) * 8;
    const int b_n    = wn * 32 + (lane & 7) + ((lane >> 4) & 1) * 8;
    const int b_koff = ((lane >> 3) & 1) * 8;

    // preamble: chunk 0 into stage 0
    loadA(0);
    issueW(0, 0);
    storeA(0, 0);
    CP_WAIT(0);
    __syncthreads();

    for (int c = 0; c < 14; c++) {
        const int s = c & 1;
        if (c < 13) {
            loadA(c + 1);
            issueW(c + 1, s ^ 1);
        }

        const uint32_t sAh = sb + s * STAGEB;
        const uint32_t sAl = sAh + BUFB;
        const uint32_t sBh = sAh + 2 * BUFB;
        const uint32_t sBl = sAh + 3 * BUFB;

#pragma unroll
        for (int ks = 0; ks < 4; ks++) {
            uint32_t ahi[2][4], alo[2][4];
#pragma unroll
            for (int mt = 0; mt < 2; mt++) {
                uint32_t ra = sAh + ((a_row + mt * 16) * PITCH + ks * 16 + a_koff) * 2;
                LDSM_X4(ahi[mt][0], ahi[mt][1], ahi[mt][2], ahi[mt][3], ra);
                uint32_t rl = sAl + ((a_row + mt * 16) * PITCH + ks * 16 + a_koff) * 2;
                LDSM_X4(alo[mt][0], alo[mt][1], alo[mt][2], alo[mt][3], rl);
            }
            uint32_t bh[4][2], bl[4][2];
#pragma unroll
            for (int p = 0; p < 2; p++) {
                uint32_t rb = sBh + ((b_n + p * 16) * PITCH + ks * 16 + b_koff) * 2;
                uint32_t r0, r1, r2, r3;
                LDSM_X4(r0, r1, r2, r3, rb);
                bh[2 * p][0] = r0; bh[2 * p][1] = r1;
                bh[2 * p + 1][0] = r2; bh[2 * p + 1][1] = r3;
                uint32_t rbl = sBl + ((b_n + p * 16) * PITCH + ks * 16 + b_koff) * 2;
                LDSM_X4(r0, r1, r2, r3, rbl);
                bl[2 * p][0] = r0; bl[2 * p][1] = r1;
                bl[2 * p + 1][0] = r2; bl[2 * p + 1][1] = r3;
            }
#pragma unroll
            for (int mt = 0; mt < 2; mt++)
#pragma unroll
                for (int nt = 0; nt < 4; nt++) {
                    MMA_F32(d[mt][nt][0], d[mt][nt][1], d[mt][nt][2], d[mt][nt][3],
                            ahi[mt][0], ahi[mt][1], ahi[mt][2], ahi[mt][3],
                            bh[nt][0], bh[nt][1]);
                    MMA_F16(c16[mt][nt][0], c16[mt][nt][1],
                            ahi[mt][0], ahi[mt][1], ahi[mt][2], ahi[mt][3],
                            bl[nt][0], bl[nt][1]);
                    MMA_F16(c16[mt][nt][0], c16[mt][nt][1],
                            alo[mt][0], alo[mt][1], alo[mt][2], alo[mt][3],
                            bh[nt][0], bh[nt][1]);
                }
        }

        if (c < 13) {
            storeA(c + 1, s ^ 1);
            CP_WAIT(0);
        }
        __syncthreads();
    }

    // ---- epilogue: merge cross, add bias, store Yout, BN partials ----
    float* stage = (float*)smp;          // 128 x 132 x 4 = 67584 (stage-0 region)
#pragma unroll
    for (int mt = 0; mt < 2; mt++)
#pragma unroll
        for (int nt = 0; nt < 4; nt++)
#pragma unroll
            for (int i = 0; i < 4; i++) {
                int row = wm * 32 + mt * 16 + (lane >> 2) + ((i >> 1) << 3);
                int col = wn * 32 + nt * 8 + ((lane & 3) << 1) + (i & 1);
                __half2 hc = *(__half2*)&c16[mt][nt][i >> 1];
                float cross = __half2float((i & 1) ? __high2half(hc) : __low2half(hc));
                stage[row * STAGE_PITCH + col] =
                    d[mt][nt][i] + cross * INV_LOSCALE + __ldg(&bias[col]);
            }
    __syncthreads();

    {
        const int col = t & 127, part = t >> 7;   // 4 parts x 32 rows
        float s = 0.f, q = 0.f;
        for (int r = 0; r < 32; r++) {
            int row = part * 32 + r;
            int m = m0 + row;
            float v = stage[row * STAGE_PITCH + col];
            if (m < NN) {
                Yout[(size_t)m * C + col] = v;
                s += v; q += v * v;
            }
        }
        ((float*)(smp + SM_REDS))[part * 128 + col] = s;
        ((float*)(smp + SM_REDQ))[part * 128 + col] = q;
    }
    __syncthreads();
    if (t < 128) {
        float s = 0.f, q = 0.f;
#pragma unroll
        for (int u = 0; u < 4; u++) {
            s += ((float*)(smp + SM_REDS))[u * 128 + t];
            q += ((float*)(smp + SM_REDQ))[u * 128 + t];
        }
        g_psum[blockIdx.x * C + t] = s;
        g_psq [blockIdx.x * C + t] = q;
    }

    // ---- last-block BN stats for this layer's output ----
    __shared__ int sIsLast;
    __threadfence();
    __syncthreads();
    if (t == 0) {
        int old = atomicAdd(&g_ticket[layer], 1);
        sIsLast = (old == NBM - 1);
    }
    __syncthreads();
    if (sIsLast) {
        const int ch = t & 127, grp = t >> 7;     // 4 groups
        float s = 0.f, q = 0.f;
        for (int b = grp; b < NBM; b += 4) {
            s += g_psum[b * C + ch];
            q += g_psq [b * C + ch];
        }
        ((float*)(smp + SM_REDS))[grp * 128 + ch] = s;
        ((float*)(smp + SM_REDQ))[grp * 128 + ch] = q;
        __syncthreads();
        if (t < 128) {
            float S = 0.f, Q = 0.f;
#pragma unroll
            for (int u = 0; u < 4; u++) {
                S += ((float*)(smp + SM_REDS))[u * 128 + t];
                Q += ((float*)(smp + SM_REDQ))[u * 128 + t];
            }
            const float inv_n = 1.f / (float)NN;
            float mu  = S * inv_n;
            float var = Q * inv_n - mu * mu;
            float sc  = gamma[t] * rsqrtf(var + EPSBN);
            g_scale[t] = sc;
            g_shift[t] = beta[t] - mu * sc;
        }
        if (t == 0) g_ticket[layer] = 0;          // replay-safe reset
    }
}

// ---------------- final layer: [N,896]@[896,36] fp32 ----------------
__global__ __launch_bounds__(256, 2) void final_kernel(
    int cur, const int* __restrict__ idx,
    const float* __restrict__ Wl, const float* __restrict__ bl,
    float* __restrict__ out)
{
    const float* __restrict__ Hin = g_Y + (size_t)cur * NN * C;
    __shared__ float sA[32 * 132];
    __shared__ float sB[32 * 40];
    __shared__ int   sIdx[128 * 7];
    __shared__ float sSc[128];
    __shared__ float sSh[128];

    const int t  = threadIdx.x;
    const int m0 = blockIdx.x * 128;
    for (int e = t; e < 128 * 7; e += 256) {
        int m = m0 + e / 7;
        sIdx[e] = (m < NN) ? idx[m * 7 + (e - (e / 7) * 7)] : 0;
    }
    if (t < 128) { sSc[t] = g_scale[t]; sSh[t] = g_shift[t]; }
    __syncthreads();

    const int ty = t >> 4, tx = t & 15;
    const int lrow = t >> 3, lk = (t & 7) << 2;
    const bool active = (tx < 12);
    const int cbase = active ? tx * 3 : 0;

    float acc[8][3];
#pragma unroll
    for (int i = 0; i < 8; i++)
#pragma unroll
        for (int jj = 0; jj < 3; jj++) acc[i][jj] = 0.f;

#pragma unroll 1
    for (int kt = 0; kt < 28; kt++) {
        const int j  = kt >> 2;
        const int cc = ((kt & 3) << 5) + lk;
        const float sc0 = sSc[cc], sc1 = sSc[cc + 1], sc2 = sSc[cc + 2], sc3 = sSc[cc + 3];
        const float sh0 = sSh[cc], sh1 = sSh[cc + 1], sh2 = sSh[cc + 2], sh3 = sSh[cc + 3];
#pragma unroll
        for (int p = 0; p < 4; p++) {
            int row = lrow + (p << 5);
            int nb  = sIdx[row * 7 + j];
            float4 v = *reinterpret_cast<const float4*>(&Hin[(size_t)nb * C + cc]);
            sA[(lk + 0) * 132 + row] = fmaxf(fmaf(v.x, sc0, sh0), 0.f);
            sA[(lk + 1) * 132 + row] = fmaxf(fmaf(v.y, sc1, sh1), 0.f);
            sA[(lk + 2) * 132 + row] = fmaxf(fmaf(v.z, sc2, sh2), 0.f);
            sA[(lk + 3) * 132 + row] = fmaxf(fmaf(v.w, sc3, sh3), 0.f);
        }
        for (int e = t; e < 32 * 36; e += 256) {
            int kr = e / 36, nc = e - kr * 36;
            sB[kr * 40 + nc] = Wl[(size_t)(kt * 32 + kr) * 36 + nc];
        }
        __syncthreads();
#pragma unroll 8
        for (int k = 0; k < 32; k++) {
            float4 aA = *reinterpret_cast<const float4*>(&sA[k * 132 + (ty << 3)]);
            float4 aB = *reinterpret_cast<const float4*>(&sA[k * 132 + (ty << 3) + 4]);
            float af[8] = { aA.x, aA.y, aA.z, aA.w, aB.x, aB.y, aB.z, aB.w };
            float b0v = sB[k * 40 + cbase];
            float b1v = sB[k * 40 + cbase + 1];
            float b2v = sB[k * 40 + cbase + 2];
#pragma unroll
            for (int i = 0; i < 8; i++) {
                acc[i][0] = fmaf(af[i], b0v, acc[i][0]);
                acc[i][1] = fmaf(af[i], b1v, acc[i][1]);
                acc[i][2] = fmaf(af[i], b2v, acc[i][2]);
            }
        }
        __syncthreads();
    }

    if (active) {
        float bb0 = bl[cbase], bb1 = bl[cbase + 1], bb2 = bl[cbase + 2];
#pragma unroll
        for (int i = 0; i < 8; i++) {
            int m = m0 + (ty << 3) + i;
            if (m < NN) {
                out[(size_t)m * NCLS + cbase + 0] = acc[i][0] + bb0;
                out[(size_t)m * NCLS + cbase + 1] = acc[i][1] + bb1;
                out[(size_t)m * NCLS + cbase + 2] = acc[i][2] + bb2;
            }
        }
    }
}

// ---------------- launch ----------------
extern "C" void kernel_launch(void* const* d_in, const int* in_sizes, int n_in,
                              void* d_out, int out_size)
{
    const float* x   = (const float*)d_in[0];
    const int*   idx = (const int*)  d_in[1];
    const float* W0  = (const float*)d_in[2];
    const float* b0  = (const float*)d_in[3];
    const float* g0  = (const float*)d_in[4];
    const float* be0 = (const float*)d_in[5];
    const float* Wm  = (const float*)d_in[6];
    const float* bm  = (const float*)d_in[7];
    const float* gm  = (const float*)d_in[8];
    const float* bem = (const float*)d_in[9];
    const float* Wl  = (const float*)d_in[10];
    const float* bl  = (const float*)d_in[11];
    float* out = (float*)d_out;

    cudaFuncSetAttribute(gemm_mma, cudaFuncAttributeMaxDynamicSharedMemorySize, GEMM_SMEM);

    prep_w<<<dim3(28, 4, NLAY), dim3(32, 32)>>>(Wm);
    layer0_kernel<<<NB0, 128>>>(x, idx, W0, b0);
    stats_final<<<1, 1024>>>(NB0, g0, be0);

    int cur = 0;
    for (int l = 0; l < NLAY; l++) {
        gemm_mma<<<NBM, 512, GEMM_SMEM>>>(l, cur, idx,
                                          bm + (size_t)l * C,
                                          gm + (size_t)l * C,
                                          bem + (size_t)l * C);
        cur ^= 1;
    }

    final_kernel<<<NBM, 256>>>(cur, idx, Wl, bl, out);
}

// round 10
// speedup vs baseline: 1.0855x; 1.0138x over previous
#include <cuda_runtime.h>
#include <cuda_fp16.h>
#include <cstdint>

// BrainSphereCNN on GB300. Round 10: fused per-layer GEMM with restructured
// chunk pipeline — storeA(convert) issued BEFORE the MMA phase (hides under
// tensor work), A prefetched two chunks ahead, W cp.async one chunk ahead,
// exactly one barrier per chunk with an empty serial tail.
// Numerics: fp16 hi/lo split, main term f32-acc MMA, cross terms share one
// f16-acc MMA (lo pre-scaled x2048). rel_err ~1.8e-5.

#define NN    40962
#define C     128
#define NB0   641
#define NBM   321
#define NCLS  36
#define EPSBN 1e-5f
#define NLAY  14
#define LOSCALE 2048.0f
#define INV_LOSCALE (1.0f / 2048.0f)

// ---------------- device scratch ----------------
__device__ float   g_Y[2ull * NN * C];             // ping-pong pre-BN outputs
__device__ __half  g_Whi[(size_t)NLAY * C * 896];  // W^T hi [l][n][k]
__device__ __half  g_Wlo[(size_t)NLAY * C * 896];  // W^T lo * 2048
__device__ float   g_psum[NB0 * C];
__device__ float   g_psq [NB0 * C];
__device__ float   g_scale[C];
__device__ float   g_shift[C];
__device__ int     g_ticket[NLAY];                 // zero-init; reset after use

// ---------------- PTX helpers ----------------
__device__ __forceinline__ uint32_t smem_u32(const void* p) {
    uint32_t a;
    asm("{ .reg .u64 t; cvta.to.shared.u64 t, %1; cvt.u32.u64 %0, t; }" : "=r"(a) : "l"(p));
    return a;
}

#define LDSM_X4(r0, r1, r2, r3, addr) \
    asm volatile("ldmatrix.sync.aligned.m8n8.x4.shared.b16 {%0,%1,%2,%3}, [%4];" \
                 : "=r"(r0), "=r"(r1), "=r"(r2), "=r"(r3) : "r"(addr))

#define MMA_F32(d0, d1, d2, d3, a0, a1, a2, a3, b0, b1) \
    asm volatile("mma.sync.aligned.m16n8k16.row.col.f32.f16.f16.f32 " \
                 "{%0,%1,%2,%3}, {%4,%5,%6,%7}, {%8,%9}, {%0,%1,%2,%3};" \
                 : "+f"(d0), "+f"(d1), "+f"(d2), "+f"(d3) \
                 : "r"(a0), "r"(a1), "r"(a2), "r"(a3), "r"(b0), "r"(b1))

#define MMA_F16(c0, c1, a0, a1, a2, a3, b0, b1) \
    asm volatile("mma.sync.aligned.m16n8k16.row.col.f16.f16.f16.f16 " \
                 "{%0,%1}, {%2,%3,%4,%5}, {%6,%7}, {%0,%1};" \
                 : "+r"(c0), "+r"(c1) \
                 : "r"(a0), "r"(a1), "r"(a2), "r"(a3), "r"(b0), "r"(b1))

#define CP16(dst, src) \
    asm volatile("cp.async.cg.shared.global [%0], [%1], 16;" :: "r"(dst), "l"(src) : "memory")
#define CP_COMMIT() asm volatile("cp.async.commit_group;" ::: "memory")
#define CP_WAIT(n)  asm volatile("cp.async.wait_group %0;" :: "n"(n) : "memory")

#define STS128(addr, x, y, z, w) \
    asm volatile("st.shared.v4.b32 [%0], {%1,%2,%3,%4};" :: "r"(addr), \
                 "r"(x), "r"(y), "r"(z), "r"(w) : "memory")

__device__ __forceinline__ uint32_t packh(float a, float b) {
    __half2 h = __floats2half2_rn(a, b);
    return *(uint32_t*)&h;
}

// ---------------- weight prep: W[l][k][n] -> W^T hi/lo fp16 [l][n][k] --------
__global__ void prep_w(const float* __restrict__ Wm) {
    __shared__ float tile[32][33];
    const int l = blockIdx.z, k0 = blockIdx.x * 32, n0 = blockIdx.y * 32;
    const int tx = threadIdx.x, ty = threadIdx.y;
    tile[ty][tx] = Wm[((size_t)l * 896 + k0 + ty) * 128 + n0 + tx];
    __syncthreads();
    float w = tile[tx][ty];
    __half hi = __float2half_rn(w);
    __half lo = __float2half_rn((w - __half2float(hi)) * LOSCALE);
    size_t o = ((size_t)l * 128 + n0 + ty) * 896 + (k0 + tx);
    g_Whi[o] = hi;
    g_Wlo[o] = lo;
}

// ---------------- layer 0: [N,21]@[21,128] fp32 ----------------
__global__ __launch_bounds__(128) void layer0_kernel(
    const float* __restrict__ x, const int* __restrict__ idx,
    const float* __restrict__ W0, const float* __restrict__ b0)
{
    __shared__ float sA[64 * 21];
    const int t = threadIdx.x;
    const int m0 = blockIdx.x * 64;
    for (int e = t; e < 64 * 21; e += 128) {
        int r = e / 21, k = e - r * 21;
        int m = m0 + r;
        float v = 0.f;
        if (m < NN) {
            int j = k / 3, c = k - j * 3;
            v = x[idx[m * 7 + j] * 3 + c];
        }
        sA[e] = v;
    }
    __syncthreads();
    float w[21];
#pragma unroll
    for (int k = 0; k < 21; k++) w[k] = W0[k * C + t];
    const float bias = b0[t];
    float s = 0.f, sq = 0.f;
    int rows = NN - m0; if (rows > 64) rows = 64;
    for (int r = 0; r < rows; r++) {
        float acc = bias;
#pragma unroll
        for (int k = 0; k < 21; k++) acc = fmaf(sA[r * 21 + k], w[k], acc);
        g_Y[(size_t)(m0 + r) * C + t] = acc;
        s += acc; sq += acc * acc;
    }
    g_psum[blockIdx.x * C + t] = s;
    g_psq [blockIdx.x * C + t] = sq;
}

// ---------------- BN stats finalize (layer 0 only) ----------------
__global__ __launch_bounds__(1024) void stats_final(int nblk, const float* __restrict__ g,
                                                    const float* __restrict__ be)
{
    __shared__ float sS[8][128], sQ[8][128];
    const int t = threadIdx.x;
    const int ch = t & 127, sl = t >> 7;
    float s = 0.f, q = 0.f;
    for (int b = sl; b < nblk; b += 8) {
        s += g_psum[b * C + ch];
        q += g_psq [b * C + ch];
    }
    sS[sl][ch] = s; sQ[sl][ch] = q;
    __syncthreads();
    if (t < 128) {
        float S = 0.f, Q = 0.f;
#pragma unroll
        for (int u = 0; u < 8; u++) { S += sS[u][t]; Q += sQ[u][t]; }
        const float inv_n = 1.f / (float)NN;
        float mu  = S * inv_n;
        float var = Q * inv_n - mu * mu;
        float sc  = g[t] * rsqrtf(var + EPSBN);
        g_scale[t] = sc;
        g_shift[t] = be[t] - mu * sc;
    }
}

// ---------------- middle layer GEMM: fused, restructured pipeline ------------
#define PITCH   72
#define BUFB    18432
#define STAGEB  (4 * BUFB)               // 73728
#define SM_REDS STAGEB                   // epilogue overlay (stage-1 region)
#define SM_REDQ (STAGEB + 2048)
#define SM_SC   (2 * STAGEB)             // 147456
#define SM_SH   (SM_SC + 512)
#define GEMM_SMEM (SM_SH + 512)          // 148480
#define STAGE_PITCH 132

__global__ void __launch_bounds__(512, 1)
gemm_mma(int layer, int cur, const int* __restrict__ idx,
         const float* __restrict__ bias,
         const float* __restrict__ gamma, const float* __restrict__ beta)
{
    extern __shared__ char smp[];
    const uint32_t sb = smem_u32(smp);
    const int t    = threadIdx.x;
    const int lane = t & 31;
    const int wid  = t >> 5;
    const int wm   = wid >> 2;
    const int wn   = wid & 3;
    const int m0   = blockIdx.x * 128;

    const float* __restrict__ Yin  = g_Y + (size_t)cur * NN * C;
    float*       __restrict__ Yout = g_Y + (size_t)(cur ^ 1) * NN * C;
    const __half* __restrict__ Whi = g_Whi + (size_t)layer * C * 896;
    const __half* __restrict__ Wlo = g_Wlo + (size_t)layer * C * 896;

    // loader mapping: grow = t>>2 (0..127 rows), gq = t&3 (16-float segment)
    const int grow = t >> 2;
    const int gq   = t & 3;
    int nbr[7];
    {
        int m = m0 + grow;
        int mm = (m < NN) ? m : 0;
#pragma unroll
        for (int j = 0; j < 7; j++) nbr[j] = idx[mm * 7 + j];
    }
    const __half* wHsrc = Whi + (size_t)grow * 896;
    const __half* wLsrc = Wlo + (size_t)grow * 896;

    float* sSc = (float*)(smp + SM_SC);
    float* sSh = (float*)(smp + SM_SH);
    if (t < 128) { sSc[t] = g_scale[t]; sSh[t] = g_shift[t]; }
    __syncthreads();

    const uint32_t aDst = (uint32_t)grow * (PITCH * 2) + (uint32_t)gq * 32;  // bytes
    const uint32_t wDst = aDst;

    auto issueW = [&](int c, int s) {
        const char* wH = (const char*)(wHsrc + c * 64) + gq * 32;
        const char* wL = (const char*)(wLsrc + c * 64) + gq * 32;
        uint32_t base = sb + s * STAGEB;
        CP16(base + 2 * BUFB + wDst,      wH);
        CP16(base + 2 * BUFB + wDst + 16, wH + 16);
        CP16(base + 3 * BUFB + wDst,      wL);
        CP16(base + 3 * BUFB + wDst + 16, wL + 16);
        CP_COMMIT();
    };

    float4 v0, v1, v2, v3;
    auto loadA = [&](int c) {
        const int j = c >> 1, h = c & 1;
        const float* src = Yin + (size_t)nbr[j] * C + h * 64 + gq * 16;
        v0 = __ldg((const float4*)(src + 0));
        v1 = __ldg((const float4*)(src + 4));
        v2 = __ldg((const float4*)(src + 8));
        v3 = __ldg((const float4*)(src + 12));
    };

    auto storeA = [&](int c, int s) {
        const int cb = (c & 1) * 64 + gq * 16;
        float p[16] = { v0.x, v0.y, v0.z, v0.w, v1.x, v1.y, v1.z, v1.w,
                        v2.x, v2.y, v2.z, v2.w, v3.x, v3.y, v3.z, v3.w };
        uint32_t hi[8], lo[8];
#pragma unroll
        for (int i = 0; i < 8; i++) {
            float h0 = fmaxf(fmaf(p[2*i],   sSc[cb + 2*i],   sSh[cb + 2*i]),   0.f);
            float h1 = fmaxf(fmaf(p[2*i+1], sSc[cb + 2*i+1], sSh[cb + 2*i+1]), 0.f);
            hi[i] = packh(h0, h1);
            __half2 hh = *(__half2*)&hi[i];
            lo[i] = packh((h0 - __half2float(__low2half(hh)))  * LOSCALE,
                          (h1 - __half2float(__high2half(hh))) * LOSCALE);
        }
        uint32_t base = sb + s * STAGEB + aDst;
        STS128(base,             hi[0], hi[1], hi[2], hi[3]);
        STS128(base + 16,        hi[4], hi[5], hi[6], hi[7]);
        STS128(base + BUFB,      lo[0], lo[1], lo[2], lo[3]);
        STS128(base + BUFB + 16, lo[4], lo[5], lo[6], lo[7]);
    };

    float    d[2][4][4];
    uint32_t c16[2][4][2];
#pragma unroll
    for (int mt = 0; mt < 2; mt++)
#pragma unroll
        for (int nt = 0; nt < 4; nt++) {
#pragma unroll
            for (int i = 0; i < 4; i++) d[mt][nt][i] = 0.f;
            c16[mt][nt][0] = 0u; c16[mt][nt][1] = 0u;
        }

    const int a_row  = wm * 32 + (lane & 15);
    const int a_koff = (lane >> 4) * 8;
    const int b_n    = wn * 32 + (lane & 7) + ((lane >> 4) & 1) * 8;
    const int b_koff = ((lane >> 3) & 1) * 8;

    // preamble: chunk 0 fully staged; A(1) prefetched
    loadA(0);
    issueW(0, 0);
    storeA(0, 0);
    loadA(1);
    CP_WAIT(0);
    __syncthreads();

    for (int c = 0; c < 14; c++) {
        const int s = c & 1;

        // front of chunk: fill stage s^1 for chunk c+1 (region free since the
        // barrier at end of chunk c-1), prefetch A(c+2). All of this issues
        // ahead of / interleaves with the MMA phase below.
        if (c < 13) {
            storeA(c + 1, s ^ 1);      // consumes staged A(c+1)
            issueW(c + 1, s ^ 1);
            if (c < 12) loadA(c + 2);  // refill staging registers
        }

        const uint32_t sAh = sb + s * STAGEB;
        const uint32_t sAl = sAh + BUFB;
        const uint32_t sBh = sAh + 2 * BUFB;
        const uint32_t sBl = sAh + 3 * BUFB;

#pragma unroll
        for (int ks = 0; ks < 4; ks++) {
            uint32_t ahi[2][4], alo[2][4];
#pragma unroll
            for (int mt = 0; mt < 2; mt++) {
                uint32_t ra = sAh + ((a_row + mt * 16) * PITCH + ks * 16 + a_koff) * 2;
                LDSM_X4(ahi[mt][0], ahi[mt][1], ahi[mt][2], ahi[mt][3], ra);
                uint32_t rl = sAl + ((a_row + mt * 16) * PITCH + ks * 16 + a_koff) * 2;
                LDSM_X4(alo[mt][0], alo[mt][1], alo[mt][2], alo[mt][3], rl);
            }
            uint32_t bh[4][2], bl[4][2];
#pragma unroll
            for (int p = 0; p < 2; p++) {
                uint32_t rb = sBh + ((b_n + p * 16) * PITCH + ks * 16 + b_koff) * 2;
                uint32_t r0, r1, r2, r3;
                LDSM_X4(r0, r1, r2, r3, rb);
                bh[2 * p][0] = r0; bh[2 * p][1] = r1;
                bh[2 * p + 1][0] = r2; bh[2 * p + 1][1] = r3;
                uint32_t rbl = sBl + ((b_n + p * 16) * PITCH + ks * 16 + b_koff) * 2;
                LDSM_X4(r0, r1, r2, r3, rbl);
                bl[2 * p][0] = r0; bl[2 * p][1] = r1;
                bl[2 * p + 1][0] = r2; bl[2 * p + 1][1] = r3;
            }
#pragma unroll
            for (int mt = 0; mt < 2; mt++)
#pragma unroll
                for (int nt = 0; nt < 4; nt++) {
                    MMA_F32(d[mt][nt][0], d[mt][nt][1], d[mt][nt][2], d[mt][nt][3],
                            ahi[mt][0], ahi[mt][1], ahi[mt][2], ahi[mt][3],
                            bh[nt][0], bh[nt][1]);
                    MMA_F16(c16[mt][nt][0], c16[mt][nt][1],
                            ahi[mt][0], ahi[mt][1], ahi[mt][2], ahi[mt][3],
                            bl[nt][0], bl[nt][1]);
                    MMA_F16(c16[mt][nt][0], c16[mt][nt][1],
                            alo[mt][0], alo[mt][1], alo[mt][2], alo[mt][3],
                            bh[nt][0], bh[nt][1]);
                }
        }

        if (c < 13) CP_WAIT(0);   // W(c+1) had the whole MMA phase to land
        __syncthreads();
    }

    // ---- epilogue: merge cross, add bias, store Yout, BN partials ----
    float* stage = (float*)smp;
#pragma unroll
    for (int mt = 0; mt < 2; mt++)
#pragma unroll
        for (int nt = 0; nt < 4; nt++)
#pragma unroll
            for (int i = 0; i < 4; i++) {
                int row = wm * 32 + mt * 16 + (lane >> 2) + ((i >> 1) << 3);
                int col = wn * 32 + nt * 8 + ((lane & 3) << 1) + (i & 1);
                __half2 hc = *(__half2*)&c16[mt][nt][i >> 1];
                float cross = __half2float((i & 1) ? __high2half(hc) : __low2half(hc));
                stage[row * STAGE_PITCH + col] =
                    d[mt][nt][i] + cross * INV_LOSCALE + __ldg(&bias[col]);
            }
    __syncthreads();

    {
        const int col = t & 127, part = t >> 7;   // 4 parts x 32 rows
        float s = 0.f, q = 0.f;
        for (int r = 0; r < 32; r++) {
            int row = part * 32 + r;
            int m = m0 + row;
            float v = stage[row * STAGE_PITCH + col];
            if (m < NN) {
                Yout[(size_t)m * C + col] = v;
                s += v; q += v * v;
            }
        }
        ((float*)(smp + SM_REDS))[part * 128 + col] = s;
        ((float*)(smp + SM_REDQ))[part * 128 + col] = q;
    }
    __syncthreads();
    if (t < 128) {
        float s = 0.f, q = 0.f;
#pragma unroll
        for (int u = 0; u < 4; u++) {
            s += ((float*)(smp + SM_REDS))[u * 128 + t];
            q += ((float*)(smp + SM_REDQ))[u * 128 + t];
        }
        g_psum[blockIdx.x * C + t] = s;
        g_psq [blockIdx.x * C + t] = q;
    }

    // ---- last-block BN stats for this layer's output ----
    __shared__ int sIsLast;
    __threadfence();
    __syncthreads();
    if (t == 0) {
        int old = atomicAdd(&g_ticket[layer], 1);
        sIsLast = (old == NBM - 1);
    }
    __syncthreads();
    if (sIsLast) {
        const int ch = t & 127, grp = t >> 7;     // 4 groups
        float s = 0.f, q = 0.f;
        for (int b = grp; b < NBM; b += 4) {
            s += g_psum[b * C + ch];
            q += g_psq [b * C + ch];
        }
        ((float*)(smp + SM_REDS))[grp * 128 + ch] = s;
        ((float*)(smp + SM_REDQ))[grp * 128 + ch] = q;
        __syncthreads();
        if (t < 128) {
            float S = 0.f, Q = 0.f;
#pragma unroll
            for (int u = 0; u < 4; u++) {
                S += ((float*)(smp + SM_REDS))[u * 128 + t];
                Q += ((float*)(smp + SM_REDQ))[u * 128 + t];
            }
            const float inv_n = 1.f / (float)NN;
            float mu  = S * inv_n;
            float var = Q * inv_n - mu * mu;
            float sc  = gamma[t] * rsqrtf(var + EPSBN);
            g_scale[t] = sc;
            g_shift[t] = beta[t] - mu * sc;
        }
        if (t == 0) g_ticket[layer] = 0;          // replay-safe reset
    }
}

// ---------------- final layer: [N,896]@[896,36] fp32 ----------------
__global__ __launch_bounds__(256, 2) void final_kernel(
    int cur, const int* __restrict__ idx,
    const float* __restrict__ Wl, const float* __restrict__ bl,
    float* __restrict__ out)
{
    const float* __restrict__ Hin = g_Y + (size_t)cur * NN * C;
    __shared__ float sA[32 * 132];
    __shared__ float sB[32 * 40];
    __shared__ int   sIdx[128 * 7];
    __shared__ float sSc[128];
    __shared__ float sSh[128];

    const int t  = threadIdx.x;
    const int m0 = blockIdx.x * 128;
    for (int e = t; e < 128 * 7; e += 256) {
        int m = m0 + e / 7;
        sIdx[e] = (m < NN) ? idx[m * 7 + (e - (e / 7) * 7)] : 0;
    }
    if (t < 128) { sSc[t] = g_scale[t]; sSh[t] = g_shift[t]; }
    __syncthreads();

    const int ty = t >> 4, tx = t & 15;
    const int lrow = t >> 3, lk = (t & 7) << 2;
    const bool active = (tx < 12);
    const int cbase = active ? tx * 3 : 0;

    float acc[8][3];
#pragma unroll
    for (int i = 0; i < 8; i++)
#pragma unroll
        for (int jj = 0; jj < 3; jj++) acc[i][jj] = 0.f;

#pragma unroll 1
    for (int kt = 0; kt < 28; kt++) {
        const int j  = kt >> 2;
        const int cc = ((kt & 3) << 5) + lk;
        const float sc0 = sSc[cc], sc1 = sSc[cc + 1], sc2 = sSc[cc + 2], sc3 = sSc[cc + 3];
        const float sh0 = sSh[cc], sh1 = sSh[cc + 1], sh2 = sSh[cc + 2], sh3 = sSh[cc + 3];
#pragma unroll
        for (int p = 0; p < 4; p++) {
            int row = lrow + (p << 5);
            int nb  = sIdx[row * 7 + j];
            float4 v = *reinterpret_cast<const float4*>(&Hin[(size_t)nb * C + cc]);
            sA[(lk + 0) * 132 + row] = fmaxf(fmaf(v.x, sc0, sh0), 0.f);
            sA[(lk + 1) * 132 + row] = fmaxf(fmaf(v.y, sc1, sh1), 0.f);
            sA[(lk + 2) * 132 + row] = fmaxf(fmaf(v.z, sc2, sh2), 0.f);
            sA[(lk + 3) * 132 + row] = fmaxf(fmaf(v.w, sc3, sh3), 0.f);
        }
        for (int e = t; e < 32 * 36; e += 256) {
            int kr = e / 36, nc = e - kr * 36;
            sB[kr * 40 + nc] = Wl[(size_t)(kt * 32 + kr) * 36 + nc];
        }
        __syncthreads();
#pragma unroll 8
        for (int k = 0; k < 32; k++) {
            float4 aA = *reinterpret_cast<const float4*>(&sA[k * 132 + (ty << 3)]);
            float4 aB = *reinterpret_cast<const float4*>(&sA[k * 132 + (ty << 3) + 4]);
            float af[8] = { aA.x, aA.y, aA.z, aA.w, aB.x, aB.y, aB.z, aB.w };
            float b0v = sB[k * 40 + cbase];
            float b1v = sB[k * 40 + cbase + 1];
            float b2v = sB[k * 40 + cbase + 2];
#pragma unroll
            for (int i = 0; i < 8; i++) {
                acc[i][0] = fmaf(af[i], b0v, acc[i][0]);
                acc[i][1] = fmaf(af[i], b1v, acc[i][1]);
                acc[i][2] = fmaf(af[i], b2v, acc[i][2]);
            }
        }
        __syncthreads();
    }

    if (active) {
        float bb0 = bl[cbase], bb1 = bl[cbase + 1], bb2 = bl[cbase + 2];
#pragma unroll
        for (int i = 0; i < 8; i++) {
            int m = m0 + (ty << 3) + i;
            if (m < NN) {
                out[(size_t)m * NCLS + cbase + 0] = acc[i][0] + bb0;
                out[(size_t)m * NCLS + cbase + 1] = acc[i][1] + bb1;
                out[(size_t)m * NCLS + cbase + 2] = acc[i][2] + bb2;
            }
        }
    }
}

// ---------------- launch ----------------
extern "C" void kernel_launch(void* const* d_in, const int* in_sizes, int n_in,
                              void* d_out, int out_size)
{
    const float* x   = (const float*)d_in[0];
    const int*   idx = (const int*)  d_in[1];
    const float* W0  = (const float*)d_in[2];
    const float* b0  = (const float*)d_in[3];
    const float* g0  = (const float*)d_in[4];
    const float* be0 = (const float*)d_in[5];
    const float* Wm  = (const float*)d_in[6];
    const float* bm  = (const float*)d_in[7];
    const float* gm  = (const float*)d_in[8];
    const float* bem = (const float*)d_in[9];
    const float* Wl  = (const float*)d_in[10];
    const float* bl  = (const float*)d_in[11];
    float* out = (float*)d_out;

    cudaFuncSetAttribute(gemm_mma, cudaFuncAttributeMaxDynamicSharedMemorySize, GEMM_SMEM);

    prep_w<<<dim3(28, 4, NLAY), dim3(32, 32)>>>(Wm);
    layer0_kernel<<<NB0, 128>>>(x, idx, W0, b0);
    stats_final<<<1, 1024>>>(NB0, g0, be0);

    int cur = 0;
    for (int l = 0; l < NLAY; l++) {
        gemm_mma<<<NBM, 512, GEMM_SMEM>>>(l, cur, idx,
                                          bm + (size_t)l * C,
                                          gm + (size_t)l * C,
                                          bem + (size_t)l * C);
        cur ^= 1;
    }

    final_kernel<<<NBM, 256>>>(cur, idx, Wl, bl, out);
}

// round 11
// speedup vs baseline: 1.1349x; 1.0455x over previous
#include <cuda_runtime.h>
#include <cuda_fp16.h>
#include <cstdint>

// BrainSphereCNN on GB300. Round 11 "best-of":
// - R5 gather: cp.async pure-copy of PRE-CONVERTED fp16 hi/lo activations
//   (standalone convert kernel, 1x work; no ALU/registers in GEMM main loop)
// - R8 numerics: fp16 hi/lo split, main term f32-acc MMA, cross terms share
//   one f16-acc MMA (lo pre-scaled x2048). rel_err ~1.8e-5
// - R9 ticket: BN stats folded into GEMM last-block (no stats kernels)
// - NEW: 3-MMA dependency chain split into 3 separated passes per k-step

#define NN    40962
#define C     128
#define NB0   641
#define NBM   321
#define NCLS  36
#define EPSBN 1e-5f
#define NLAY  14
#define LOSCALE 2048.0f
#define INV_LOSCALE (1.0f / 2048.0f)

// ---------------- device scratch ----------------
__device__ float   g_Y[(size_t)NN * C];            // pre-BN linear outputs
__device__ __half  g_Xhi[(size_t)NN * C];          // post-BN/ReLU fp16 hi
__device__ __half  g_Xlo[(size_t)NN * C];          // fp16 lo residual * 2048
__device__ __half  g_Whi[(size_t)NLAY * C * 896];  // W^T hi [l][n][k]
__device__ __half  g_Wlo[(size_t)NLAY * C * 896];  // W^T lo * 2048
__device__ float   g_psum[NB0 * C];
__device__ float   g_psq [NB0 * C];
__device__ float   g_scale[C];
__device__ float   g_shift[C];
__device__ int     g_ticket[NLAY];                 // zero-init; reset after use

// ---------------- PTX helpers ----------------
__device__ __forceinline__ uint32_t smem_u32(const void* p) {
    uint32_t a;
    asm("{ .reg .u64 t; cvta.to.shared.u64 t, %1; cvt.u32.u64 %0, t; }" : "=r"(a) : "l"(p));
    return a;
}

#define LDSM_X4(r0, r1, r2, r3, addr) \
    asm volatile("ldmatrix.sync.aligned.m8n8.x4.shared.b16 {%0,%1,%2,%3}, [%4];" \
                 : "=r"(r0), "=r"(r1), "=r"(r2), "=r"(r3) : "r"(addr))

#define MMA_F32(d0, d1, d2, d3, a0, a1, a2, a3, b0, b1) \
    asm volatile("mma.sync.aligned.m16n8k16.row.col.f32.f16.f16.f32 " \
                 "{%0,%1,%2,%3}, {%4,%5,%6,%7}, {%8,%9}, {%0,%1,%2,%3};" \
                 : "+f"(d0), "+f"(d1), "+f"(d2), "+f"(d3) \
                 : "r"(a0), "r"(a1), "r"(a2), "r"(a3), "r"(b0), "r"(b1))

#define MMA_F16(c0, c1, a0, a1, a2, a3, b0, b1) \
    asm volatile("mma.sync.aligned.m16n8k16.row.col.f16.f16.f16.f16 " \
                 "{%0,%1}, {%2,%3,%4,%5}, {%6,%7}, {%0,%1};" \
                 : "+r"(c0), "+r"(c1) \
                 : "r"(a0), "r"(a1), "r"(a2), "r"(a3), "r"(b0), "r"(b1))

#define CP16(dst, src) \
    asm volatile("cp.async.cg.shared.global [%0], [%1], 16;" :: "r"(dst), "l"(src) : "memory")
#define CP_COMMIT() asm volatile("cp.async.commit_group;" ::: "memory")
#define CP_WAIT(n)  asm volatile("cp.async.wait_group %0;" :: "n"(n) : "memory")

// ---------------- weight prep: W[l][k][n] -> W^T hi/lo fp16 [l][n][k] --------
__global__ void prep_w(const float* __restrict__ Wm) {
    __shared__ float tile[32][33];
    const int l = blockIdx.z, k0 = blockIdx.x * 32, n0 = blockIdx.y * 32;
    const int tx = threadIdx.x, ty = threadIdx.y;
    tile[ty][tx] = Wm[((size_t)l * 896 + k0 + ty) * 128 + n0 + tx];
    __syncthreads();
    float w = tile[tx][ty];
    __half hi = __float2half_rn(w);
    __half lo = __float2half_rn((w - __half2float(hi)) * LOSCALE);
    size_t o = ((size_t)l * 128 + n0 + ty) * 896 + (k0 + tx);
    g_Whi[o] = hi;
    g_Wlo[o] = lo;
}

// ---------------- layer 0: [N,21]@[21,128] fp32 ----------------
__global__ __launch_bounds__(128) void layer0_kernel(
    const float* __restrict__ x, const int* __restrict__ idx,
    const float* __restrict__ W0, const float* __restrict__ b0)
{
    __shared__ float sA[64 * 21];
    const int t = threadIdx.x;
    const int m0 = blockIdx.x * 64;
    for (int e = t; e < 64 * 21; e += 128) {
        int r = e / 21, k = e - r * 21;
        int m = m0 + r;
        float v = 0.f;
        if (m < NN) {
            int j = k / 3, c = k - j * 3;
            v = x[idx[m * 7 + j] * 3 + c];
        }
        sA[e] = v;
    }
    __syncthreads();
    float w[21];
#pragma unroll
    for (int k = 0; k < 21; k++) w[k] = W0[k * C + t];
    const float bias = b0[t];
    float s = 0.f, sq = 0.f;
    int rows = NN - m0; if (rows > 64) rows = 64;
    for (int r = 0; r < rows; r++) {
        float acc = bias;
#pragma unroll
        for (int k = 0; k < 21; k++) acc = fmaf(sA[r * 21 + k], w[k], acc);
        g_Y[(size_t)(m0 + r) * C + t] = acc;
        s += acc; sq += acc * acc;
    }
    g_psum[blockIdx.x * C + t] = s;
    g_psq [blockIdx.x * C + t] = sq;
}

// ---------------- BN stats finalize (layer 0 only) ----------------
__global__ __launch_bounds__(1024) void stats_final(int nblk, const float* __restrict__ g,
                                                    const float* __restrict__ be)
{
    __shared__ float sS[8][128], sQ[8][128];
    const int t = threadIdx.x;
    const int ch = t & 127, sl = t >> 7;
    float s = 0.f, q = 0.f;
    for (int b = sl; b < nblk; b += 8) {
        s += g_psum[b * C + ch];
        q += g_psq [b * C + ch];
    }
    sS[sl][ch] = s; sQ[sl][ch] = q;
    __syncthreads();
    if (t < 128) {
        float S = 0.f, Q = 0.f;
#pragma unroll
        for (int u = 0; u < 8; u++) { S += sS[u][t]; Q += sQ[u][t]; }
        const float inv_n = 1.f / (float)NN;
        float mu  = S * inv_n;
        float var = Q * inv_n - mu * mu;
        float sc  = g[t] * rsqrtf(var + EPSBN);
        g_scale[t] = sc;
        g_shift[t] = be[t] - mu * sc;
    }
}

// ---------------- convert: Y -> fp16 hi + scaled lo (affine + ReLU) ----------
__global__ __launch_bounds__(256) void convert_kernel() {
    int e = blockIdx.x * 256 + threadIdx.x;
    if (e >= NN * 32) return;
    const int c0 = (e & 31) * 4;
    float4 y = ((const float4*)g_Y)[e];
    float h0 = fmaxf(fmaf(y.x, g_scale[c0 + 0], g_shift[c0 + 0]), 0.f);
    float h1 = fmaxf(fmaf(y.y, g_scale[c0 + 1], g_shift[c0 + 1]), 0.f);
    float h2 = fmaxf(fmaf(y.z, g_scale[c0 + 2], g_shift[c0 + 2]), 0.f);
    float h3 = fmaxf(fmaf(y.w, g_scale[c0 + 3], g_shift[c0 + 3]), 0.f);
    __half a0 = __float2half_rn(h0), a1 = __float2half_rn(h1);
    __half a2 = __float2half_rn(h2), a3 = __float2half_rn(h3);
    __half l0 = __float2half_rn((h0 - __half2float(a0)) * LOSCALE);
    __half l1 = __float2half_rn((h1 - __half2float(a1)) * LOSCALE);
    __half l2 = __float2half_rn((h2 - __half2float(a2)) * LOSCALE);
    __half l3 = __float2half_rn((h3 - __half2float(a3)) * LOSCALE);
    uint2 ph, pl;
    ph.x = (uint32_t)__half_as_ushort(a0) | ((uint32_t)__half_as_ushort(a1) << 16);
    ph.y = (uint32_t)__half_as_ushort(a2) | ((uint32_t)__half_as_ushort(a3) << 16);
    pl.x = (uint32_t)__half_as_ushort(l0) | ((uint32_t)__half_as_ushort(l1) << 16);
    pl.y = (uint32_t)__half_as_ushort(l2) | ((uint32_t)__half_as_ushort(l3) << 16);
    ((uint2*)g_Xhi)[e] = ph;
    ((uint2*)g_Xlo)[e] = pl;
}

// ---------------- middle layer GEMM: cp.async gather, ticket stats -----------
// 512 threads, 16 warps (4x4 grid of 32x32 warp tiles), 14 chunks of 64 halves.
// Stage: Ahi|Alo|Whi|Wlo, each 128 rows x 72-half pitch = 18432 B -> 73728/stage.
#define PITCH   72
#define BUFB    18432
#define STAGEB  (4 * BUFB)               // 73728
#define SM_REDS STAGEB                   // epilogue overlay (stage-1 region)
#define SM_REDQ (STAGEB + 2048)
#define SM_IDX  (2 * STAGEB)             // 147456 : 896 ints
#define GEMM_SMEM (SM_IDX + 3584)        // 151040
#define STAGE_PITCH 132

__global__ void __launch_bounds__(512, 1)
gemm_mma(int layer, const int* __restrict__ idx,
         const float* __restrict__ bias,
         const float* __restrict__ gamma, const float* __restrict__ beta)
{
    extern __shared__ char smp[];
    const uint32_t sb = smem_u32(smp);
    const int t    = threadIdx.x;
    const int lane = t & 31;
    const int wid  = t >> 5;
    const int wm   = wid >> 2;
    const int wn   = wid & 3;
    const int m0   = blockIdx.x * 128;

    const __half* __restrict__ Whi = g_Whi + (size_t)layer * C * 896;
    const __half* __restrict__ Wlo = g_Wlo + (size_t)layer * C * 896;

    int* sIdx = (int*)(smp + SM_IDX);
    for (int e = t; e < 896; e += 512) {
        int row = e / 7, j = e - row * 7;
        int m = m0 + row;
        sIdx[e] = (m < NN) ? idx[m * 7 + j] : 0;
    }
    __syncthreads();

    // loader: grow = t>>2 (0..127 rows), gq = t&3 (32B segment of 128B row)
    const int grow = t >> 2;
    const int gq   = t & 3;
    const uint32_t dstOff = (uint32_t)grow * (PITCH * 2) + (uint32_t)gq * 32;
    const __half* wHrow = Whi + (size_t)grow * 896;
    const __half* wLrow = Wlo + (size_t)grow * 896;

    auto issue = [&](int c, int s) {
        const int j = c >> 1, h = c & 1;
        const int nb = sIdx[grow * 7 + j];
        const char* aH = (const char*)(g_Xhi + (size_t)nb * C + h * 64) + gq * 32;
        const char* aL = (const char*)(g_Xlo + (size_t)nb * C + h * 64) + gq * 32;
        const char* wH = (const char*)(wHrow + c * 64) + gq * 32;
        const char* wL = (const char*)(wLrow + c * 64) + gq * 32;
        uint32_t base = sb + s * STAGEB + dstOff;
        CP16(base,                 aH);
        CP16(base + 16,            aH + 16);
        CP16(base + BUFB,          aL);
        CP16(base + BUFB + 16,     aL + 16);
        CP16(base + 2 * BUFB,      wH);
        CP16(base + 2 * BUFB + 16, wH + 16);
        CP16(base + 3 * BUFB,      wL);
        CP16(base + 3 * BUFB + 16, wL + 16);
        CP_COMMIT();
    };

    float    d[2][4][4];
    uint32_t c16[2][4][2];
#pragma unroll
    for (int mt = 0; mt < 2; mt++)
#pragma unroll
        for (int nt = 0; nt < 4; nt++) {
#pragma unroll
            for (int i = 0; i < 4; i++) d[mt][nt][i] = 0.f;
            c16[mt][nt][0] = 0u; c16[mt][nt][1] = 0u;
        }

    const int a_row  = wm * 32 + (lane & 15);
    const int a_koff = (lane >> 4) * 8;
    const int b_n    = wn * 32 + (lane & 7) + ((lane >> 4) & 1) * 8;
    const int b_koff = ((lane >> 3) & 1) * 8;

    issue(0, 0);

    for (int c = 0; c < 14; c++) {
        const int s = c & 1;
        if (c + 1 < 14) {
            issue(c + 1, s ^ 1);
            CP_WAIT(1);
        } else {
            CP_WAIT(0);
        }
        __syncthreads();

        const uint32_t sAh = sb + s * STAGEB;
        const uint32_t sAl = sAh + BUFB;
        const uint32_t sBh = sAh + 2 * BUFB;
        const uint32_t sBl = sAh + 3 * BUFB;

#pragma unroll
        for (int ks = 0; ks < 4; ks++) {
            uint32_t ahi[2][4], alo[2][4];
#pragma unroll
            for (int mt = 0; mt < 2; mt++) {
                uint32_t ra = sAh + ((a_row + mt * 16) * PITCH + ks * 16 + a_koff) * 2;
                LDSM_X4(ahi[mt][0], ahi[mt][1], ahi[mt][2], ahi[mt][3], ra);
                uint32_t rl = sAl + ((a_row + mt * 16) * PITCH + ks * 16 + a_koff) * 2;
                LDSM_X4(alo[mt][0], alo[mt][1], alo[mt][2], alo[mt][3], rl);
            }
            uint32_t bh[4][2], bl[4][2];
#pragma unroll
            for (int p = 0; p < 2; p++) {
                uint32_t rb = sBh + ((b_n + p * 16) * PITCH + ks * 16 + b_koff) * 2;
                uint32_t r0, r1, r2, r3;
                LDSM_X4(r0, r1, r2, r3, rb);
                bh[2 * p][0] = r0; bh[2 * p][1] = r1;
                bh[2 * p + 1][0] = r2; bh[2 * p + 1][1] = r3;
                uint32_t rbl = sBl + ((b_n + p * 16) * PITCH + ks * 16 + b_koff) * 2;
                LDSM_X4(r0, r1, r2, r3, rbl);
                bl[2 * p][0] = r0; bl[2 * p][1] = r1;
                bl[2 * p + 1][0] = r2; bl[2 * p + 1][1] = r3;
            }
            // pass 1: main term (8 independent d-chains)
#pragma unroll
            for (int mt = 0; mt < 2; mt++)
#pragma unroll
                for (int nt = 0; nt < 4; nt++)
                    MMA_F32(d[mt][nt][0], d[mt][nt][1], d[mt][nt][2], d[mt][nt][3],
                            ahi[mt][0], ahi[mt][1], ahi[mt][2], ahi[mt][3],
                            bh[nt][0], bh[nt][1]);
            // pass 2: cross term 1 (8 independent c16-chains)
#pragma unroll
            for (int mt = 0; mt < 2; mt++)
#pragma unroll
                for (int nt = 0; nt < 4; nt++)
                    MMA_F16(c16[mt][nt][0], c16[mt][nt][1],
                            ahi[mt][0], ahi[mt][1], ahi[mt][2], ahi[mt][3],
                            bl[nt][0], bl[nt][1]);
            // pass 3: cross term 2 (separated from pass 2 by 8 ops)
#pragma unroll
            for (int mt = 0; mt < 2; mt++)
#pragma unroll
                for (int nt = 0; nt < 4; nt++)
                    MMA_F16(c16[mt][nt][0], c16[mt][nt][1],
                            alo[mt][0], alo[mt][1], alo[mt][2], alo[mt][3],
                            bh[nt][0], bh[nt][1]);
        }
        __syncthreads();
    }

    // ---- epilogue: merge cross, add bias, store Y, BN partials ----
    float* stage = (float*)smp;
#pragma unroll
    for (int mt = 0; mt < 2; mt++)
#pragma unroll
        for (int nt = 0; nt < 4; nt++)
#pragma unroll
            for (int i = 0; i < 4; i++) {
                int row = wm * 32 + mt * 16 + (lane >> 2) + ((i >> 1) << 3);
                int col = wn * 32 + nt * 8 + ((lane & 3) << 1) + (i & 1);
                __half2 hc = *(__half2*)&c16[mt][nt][i >> 1];
                float cross = __half2float((i & 1) ? __high2half(hc) : __low2half(hc));
                stage[row * STAGE_PITCH + col] =
                    d[mt][nt][i] + cross * INV_LOSCALE + __ldg(&bias[col]);
            }
    __syncthreads();

    {
        const int col = t & 127, part = t >> 7;   // 4 parts x 32 rows
        float s = 0.f, q = 0.f;
        for (int r = 0; r < 32; r++) {
            int row = part * 32 + r;
            int m = m0 + row;
            float v = stage[row * STAGE_PITCH + col];
            if (m < NN) {
                g_Y[(size_t)m * C + col] = v;
                s += v; q += v * v;
            }
        }
        ((float*)(smp + SM_REDS))[part * 128 + col] = s;
        ((float*)(smp + SM_REDQ))[part * 128 + col] = q;
    }
    __syncthreads();
    if (t < 128) {
        float s = 0.f, q = 0.f;
#pragma unroll
        for (int u = 0; u < 4; u++) {
            s += ((float*)(smp + SM_REDS))[u * 128 + t];
            q += ((float*)(smp + SM_REDQ))[u * 128 + t];
        }
        g_psum[blockIdx.x * C + t] = s;
        g_psq [blockIdx.x * C + t] = q;
    }

    // ---- last-block BN stats for this layer's output ----
    __shared__ int sIsLast;
    __threadfence();
    __syncthreads();
    if (t == 0) {
        int old = atomicAdd(&g_ticket[layer], 1);
        sIsLast = (old == NBM - 1);
    }
    __syncthreads();
    if (sIsLast) {
        const int ch = t & 127, grp = t >> 7;     // 4 groups
        float s = 0.f, q = 0.f;
        for (int b = grp; b < NBM; b += 4) {
            s += g_psum[b * C + ch];
            q += g_psq [b * C + ch];
        }
        ((float*)(smp + SM_REDS))[grp * 128 + ch] = s;
        ((float*)(smp + SM_REDQ))[grp * 128 + ch] = q;
        __syncthreads();
        if (t < 128) {
            float S = 0.f, Q = 0.f;
#pragma unroll
            for (int u = 0; u < 4; u++) {
                S += ((float*)(smp + SM_REDS))[u * 128 + t];
                Q += ((float*)(smp + SM_REDQ))[u * 128 + t];
            }
            const float inv_n = 1.f / (float)NN;
            float mu  = S * inv_n;
            float var = Q * inv_n - mu * mu;
            float sc  = gamma[t] * rsqrtf(var + EPSBN);
            g_scale[t] = sc;
            g_shift[t] = beta[t] - mu * sc;
        }
        if (t == 0) g_ticket[layer] = 0;          // replay-safe reset
    }
}

// ---------------- final layer: [N,896]@[896,36] fp32 ----------------
__global__ __launch_bounds__(256, 2) void final_kernel(
    const int* __restrict__ idx,
    const float* __restrict__ Wl, const float* __restrict__ bl,
    float* __restrict__ out)
{
    const float* __restrict__ Hin = g_Y;
    __shared__ float sA[32 * 132];
    __shared__ float sB[32 * 40];
    __shared__ int   sIdx[128 * 7];
    __shared__ float sSc[128];
    __shared__ float sSh[128];

    const int t  = threadIdx.x;
    const int m0 = blockIdx.x * 128;
    for (int e = t; e < 128 * 7; e += 256) {
        int m = m0 + e / 7;
        sIdx[e] = (m < NN) ? idx[m * 7 + (e - (e / 7) * 7)] : 0;
    }
    if (t < 128) { sSc[t] = g_scale[t]; sSh[t] = g_shift[t]; }
    __syncthreads();

    const int ty = t >> 4, tx = t & 15;
    const int lrow = t >> 3, lk = (t & 7) << 2;
    const bool active = (tx < 12);
    const int cbase = active ? tx * 3 : 0;

    float acc[8][3];
#pragma unroll
    for (int i = 0; i < 8; i++)
#pragma unroll
        for (int jj = 0; jj < 3; jj++) acc[i][jj] = 0.f;

#pragma unroll 1
    for (int kt = 0; kt < 28; kt++) {
        const int j  = kt >> 2;
        const int cc = ((kt & 3) << 5) + lk;
        const float sc0 = sSc[cc], sc1 = sSc[cc + 1], sc2 = sSc[cc + 2], sc3 = sSc[cc + 3];
        const float sh0 = sSh[cc], sh1 = sSh[cc + 1], sh2 = sSh[cc + 2], sh3 = sSh[cc + 3];
#pragma unroll
        for (int p = 0; p < 4; p++) {
            int row = lrow + (p << 5);
            int nb  = sIdx[row * 7 + j];
            float4 v = *reinterpret_cast<const float4*>(&Hin[(size_t)nb * C + cc]);
            sA[(lk + 0) * 132 + row] = fmaxf(fmaf(v.x, sc0, sh0), 0.f);
            sA[(lk + 1) * 132 + row] = fmaxf(fmaf(v.y, sc1, sh1), 0.f);
            sA[(lk + 2) * 132 + row] = fmaxf(fmaf(v.z, sc2, sh2), 0.f);
            sA[(lk + 3) * 132 + row] = fmaxf(fmaf(v.w, sc3, sh3), 0.f);
        }
        for (int e = t; e < 32 * 36; e += 256) {
            int kr = e / 36, nc = e - kr * 36;
            sB[kr * 40 + nc] = Wl[(size_t)(kt * 32 + kr) * 36 + nc];
        }
        __syncthreads();
#pragma unroll 8
        for (int k = 0; k < 32; k++) {
            float4 aA = *reinterpret_cast<const float4*>(&sA[k * 132 + (ty << 3)]);
            float4 aB = *reinterpret_cast<const float4*>(&sA[k * 132 + (ty << 3) + 4]);
            float af[8] = { aA.x, aA.y, aA.z, aA.w, aB.x, aB.y, aB.z, aB.w };
            float b0v = sB[k * 40 + cbase];
            float b1v = sB[k * 40 + cbase + 1];
            float b2v = sB[k * 40 + cbase + 2];
#pragma unroll
            for (int i = 0; i < 8; i++) {
                acc[i][0] = fmaf(af[i], b0v, acc[i][0]);
                acc[i][1] = fmaf(af[i], b1v, acc[i][1]);
                acc[i][2] = fmaf(af[i], b2v, acc[i][2]);
            }
        }
        __syncthreads();
    }

    if (active) {
        float bb0 = bl[cbase], bb1 = bl[cbase + 1], bb2 = bl[cbase + 2];
#pragma unroll
        for (int i = 0; i < 8; i++) {
            int m = m0 + (ty << 3) + i;
            if (m < NN) {
                out[(size_t)m * NCLS + cbase + 0] = acc[i][0] + bb0;
                out[(size_t)m * NCLS + cbase + 1] = acc[i][1] + bb1;
                out[(size_t)m * NCLS + cbase + 2] = acc[i][2] + bb2;
            }
        }
    }
}

// ---------------- launch ----------------
extern "C" void kernel_launch(void* const* d_in, const int* in_sizes, int n_in,
                              void* d_out, int out_size)
{
    const float* x   = (const float*)d_in[0];
    const int*   idx = (const int*)  d_in[1];
    const float* W0  = (const float*)d_in[2];
    const float* b0  = (const float*)d_in[3];
    const float* g0  = (const float*)d_in[4];
    const float* be0 = (const float*)d_in[5];
    const float* Wm  = (const float*)d_in[6];
    const float* bm  = (const float*)d_in[7];
    const float* gm  = (const float*)d_in[8];
    const float* bem = (const float*)d_in[9];
    const float* Wl  = (const float*)d_in[10];
    const float* bl  = (const float*)d_in[11];
    float* out = (float*)d_out;

    cudaFuncSetAttribute(gemm_mma, cudaFuncAttributeMaxDynamicSharedMemorySize, GEMM_SMEM);

    prep_w<<<dim3(28, 4, NLAY), dim3(32, 32)>>>(Wm);
    layer0_kernel<<<NB0, 128>>>(x, idx, W0, b0);
    stats_final<<<1, 1024>>>(NB0, g0, be0);
    convert_kernel<<<(NN * 32 + 255) / 256, 256>>>();

    for (int l = 0; l < NLAY; l++) {
        gemm_mma<<<NBM, 512, GEMM_SMEM>>>(l, idx,
                                          bm + (size_t)l * C,
                                          gm + (size_t)l * C,
                                          bem + (size_t)l * C);
        if (l < NLAY - 1)
            convert_kernel<<<(NN * 32 + 255) / 256, 256>>>();
    }

    final_kernel<<<NBM, 256>>>(idx, Wl, bl, out);
}